// round 8
// baseline (speedup 1.0000x reference)
#include <cuda_runtime.h>
#include <math.h>
#include <stdint.h>

// Problem dims (fixed)
#define BB   16
#define LL   2048
#define HH   256
#define NN   64
#define NLAY 4
#define IND  40
#define OUTD 33

// Chunked-scan config: 2 chunks of 1024; scan2 sub-splits into 512-step units
#define CH    2
#define CLEN  1024
#define HALF  512

typedef unsigned long long ull;

// ------------------------------------------------------------------
// Scratch (device globals)
// ------------------------------------------------------------------
__device__ float g_h[BB * LL * HH];   // residual stream, [m][h]
__device__ float g_zt[BB * HH * LL];  // layernorm output, TRANSPOSED [seq][l]
__device__ float g_yt[BB * HH * LL];  // SSM/gelu output, TRANSPOSED [seq][l]
__device__ float g_ar[HH * NN];
__device__ float g_ai[HH * NN];
__device__ float g_wr[HH * NN];
__device__ float g_win[HH * NN];
__device__ float g_apr[HH * NN];      // Re(dA^HALF)
__device__ float g_api[HH * NN];      // Im(dA^HALF)
__device__ float g_esr[BB * HH * CH * NN];
__device__ float g_esi[BB * HH * CH * NN];

// ------------------------------------------------------------------
// f32x2 packed math (Blackwell)
// ------------------------------------------------------------------
__device__ __forceinline__ ull pk2(float lo, float hi) {
    ull r;
    asm("mov.b64 %0, {%1, %2};" : "=l"(r) : "f"(lo), "f"(hi));
    return r;
}
__device__ __forceinline__ void upk2(ull v, float& lo, float& hi) {
    asm("mov.b64 {%0, %1}, %2;" : "=f"(lo), "=f"(hi) : "l"(v));
}
__device__ __forceinline__ ull fma2(ull a, ull b, ull c) {
    ull d;
    asm("fma.rn.f32x2 %0, %1, %2, %3;" : "=l"(d) : "l"(a), "l"(b), "l"(c));
    return d;
}
__device__ __forceinline__ ull mul2(ull a, ull b) {
    ull d;
    asm("mul.rn.f32x2 %0, %1, %2;" : "=l"(d) : "l"(a), "l"(b));
    return d;
}
__device__ __forceinline__ ull add2(ull a, ull b) {
    ull d;
    asm("add.rn.f32x2 %0, %1, %2;" : "=l"(d) : "l"(a), "l"(b));
    return d;
}

__device__ __forceinline__ float gelu1(float x) {
    const float c0 = 0.7978845608028654f;
    const float c1 = 0.044715f;
    float t = tanhf(c0 * (x + c1 * x * x * x));
    return 0.5f * x * (1.0f + t);
}

__device__ __forceinline__ uint32_t f2tf32(float x) {
    uint32_t r;
    asm("cvt.rna.tf32.f32 %0, %1;" : "=r"(r) : "f"(x));
    return r;
}

// mma.sync tf32 m16n8k8 (sm_80+, valid on target sm_103)
__device__ __forceinline__ void mma_tf32(float c[4],
                                         uint32_t a0, uint32_t a1,
                                         uint32_t a2, uint32_t a3,
                                         uint32_t b0, uint32_t b1) {
    asm volatile(
        "mma.sync.aligned.m16n8k8.row.col.f32.tf32.tf32.f32 "
        "{%0,%1,%2,%3}, {%4,%5,%6,%7}, {%8,%9}, {%0,%1,%2,%3};"
        : "+f"(c[0]), "+f"(c[1]), "+f"(c[2]), "+f"(c[3])
        : "r"(a0), "r"(a1), "r"(a2), "r"(a3), "r"(b0), "r"(b1));
}

// ------------------------------------------------------------------
// Encoder
// ------------------------------------------------------------------
__global__ void enc_kernel(const float* __restrict__ x,
                           const float* __restrict__ ew,
                           const float* __restrict__ eb) {
    __shared__ float sw[IND * HH];
    __shared__ float sx[16 * IND];
    int tid = threadIdx.x;
    for (int idx = tid; idx < HH * IND; idx += 256) {
        int h = idx / IND, i = idx % IND;
        sw[i * HH + h] = ew[idx];
    }
    int m0 = blockIdx.x * 16;
    for (int idx = tid; idx < 16 * IND; idx += 256)
        sx[idx] = x[(size_t)m0 * IND + idx];
    __syncthreads();
    float bias = eb[tid];
    for (int r = 0; r < 16; ++r) {
        float acc = bias;
        #pragma unroll
        for (int i = 0; i < IND; ++i)
            acc = fmaf(sx[r * IND + i], sw[i * HH + tid], acc);
        g_h[(size_t)(m0 + r) * HH + tid] = acc;
    }
}

// ------------------------------------------------------------------
// LayerNorm + transpose
// ------------------------------------------------------------------
__global__ void ln_kernel(const float* __restrict__ sc,
                          const float* __restrict__ bi) {
    __shared__ float sm[32][257];
    int tid  = threadIdx.x;
    int warp = tid >> 5;
    int lane = tid & 31;
    int m0 = blockIdx.x * 32;

    for (int r = warp; r < 32; r += 8) {
        const float* row = g_h + (size_t)(m0 + r) * HH;
        float4 v0 = *reinterpret_cast<const float4*>(row + lane * 4);
        float4 v1 = *reinterpret_cast<const float4*>(row + 128 + lane * 4);
        float s = v0.x + v0.y + v0.z + v0.w + v1.x + v1.y + v1.z + v1.w;
        float q = v0.x*v0.x + v0.y*v0.y + v0.z*v0.z + v0.w*v0.w
                + v1.x*v1.x + v1.y*v1.y + v1.z*v1.z + v1.w*v1.w;
        #pragma unroll
        for (int m = 16; m; m >>= 1) {
            s += __shfl_xor_sync(0xffffffffu, s, m);
            q += __shfl_xor_sync(0xffffffffu, q, m);
        }
        float mu  = s * (1.0f / 256.0f);
        float var = q * (1.0f / 256.0f) - mu * mu;
        float inv = rsqrtf(var + 1e-5f);
        int h0 = lane * 4, h1 = 128 + lane * 4;
        sm[r][h0+0] = (v0.x - mu) * inv * sc[h0+0] + bi[h0+0];
        sm[r][h0+1] = (v0.y - mu) * inv * sc[h0+1] + bi[h0+1];
        sm[r][h0+2] = (v0.z - mu) * inv * sc[h0+2] + bi[h0+2];
        sm[r][h0+3] = (v0.w - mu) * inv * sc[h0+3] + bi[h0+3];
        sm[r][h1+0] = (v1.x - mu) * inv * sc[h1+0] + bi[h1+0];
        sm[r][h1+1] = (v1.y - mu) * inv * sc[h1+1] + bi[h1+1];
        sm[r][h1+2] = (v1.z - mu) * inv * sc[h1+2] + bi[h1+2];
        sm[r][h1+3] = (v1.w - mu) * inv * sc[h1+3] + bi[h1+3];
    }
    __syncthreads();

    int b  = m0 >> 11;
    int l0 = m0 & 2047;
    for (int h = warp; h < HH; h += 8) {
        g_zt[((size_t)(b * HH + h)) * LL + l0 + lane] = sm[lane][h];
    }
}

// ------------------------------------------------------------------
// S4D discretization + dA^HALF (double)
// ------------------------------------------------------------------
__global__ void ssm_params_kernel(const float* __restrict__ lre,
                                  const float* __restrict__ lim,
                                  const float* __restrict__ cre,
                                  const float* __restrict__ cim,
                                  const float* __restrict__ lstep) {
    int idx = blockIdx.x * blockDim.x + threadIdx.x;
    if (idx >= HH * NN) return;
    int h = idx >> 6;
    float Lre = lre[idx], Lim = lim[idx];
    float Cre = cre[idx], Cim = cim[idx];
    float dt  = expf(lstep[h]);
    float mag = expf(Lre * dt);
    float th  = Lim * dt;
    float dar = mag * cosf(th);
    float dai = mag * sinf(th);
    float den = Lre * Lre + Lim * Lim;
    float nr = dar - 1.0f, ni = dai;
    float dbr = (nr * Lre + ni * Lim) / den;
    float dbi = (ni * Lre - nr * Lim) / den;
    float wr = Cre * dbr - Cim * dbi;
    float wi = Cre * dbi + Cim * dbr;
    g_ar[idx]  = dar;
    g_ai[idx]  = dai;
    g_wr[idx]  = 2.0f * wr;
    g_win[idx] = -2.0f * wi;
    double dtd = exp((double)lstep[h]);
    double mr  = exp((double)Lre * dtd * (double)HALF);
    double thd = (double)Lim * dtd * (double)HALF;
    g_apr[idx] = (float)(mr * cos(thd));
    g_api[idx] = (float)(mr * sin(thd));
}

// ------------------------------------------------------------------
// Scan pass 1 (R5 configuration): 2 units/warp, 16 lanes/unit,
// 4 complex states/lane, 16-step tiles + reduce-scatter,
// fused gelu on chunk 0.  CH=2, CLEN=1024.
// ------------------------------------------------------------------
__global__ void __launch_bounds__(256, 4) scan1_kernel(const float* __restrict__ dcoef) {
    int warp = (blockIdx.x * blockDim.x + threadIdx.x) >> 5;
    int lane = threadIdx.x & 31;
    int half = lane >> 4;
    int ln   = lane & 15;
    int unit = warp * 2 + half;        // 0..B*H*CH-1
    int seq  = unit >> 1;              // unit / CH
    int c    = unit & (CH - 1);
    int h = seq & 255;
    int base = h * NN + ln * 4;

    float a0r = g_ar[base+0], a1r = g_ar[base+1], a2r = g_ar[base+2], a3r = g_ar[base+3];
    float a0i = g_ai[base+0], a1i = g_ai[base+1], a2i = g_ai[base+2], a3i = g_ai[base+3];
    float w0r = g_wr[base+0], w1r = g_wr[base+1], w2r = g_wr[base+2], w3r = g_wr[base+3];
    float w0n = g_win[base+0], w1n = g_win[base+1], w2n = g_win[base+2], w3n = g_win[base+3];

    ull ar01 = pk2(a0r, a1r), ar23 = pk2(a2r, a3r);
    ull ai01 = pk2(a0i, a1i), ai23 = pk2(a2i, a3i);
    ull an01 = pk2(-a0i, -a1i), an23 = pk2(-a2i, -a3i);
    ull wr01 = pk2(w0r, w1r), wr23 = pk2(w2r, w3r);
    ull wn01 = pk2(w0n, w1n), wn23 = pk2(w2n, w3n);

    ull sr01 = 0ULL, si01 = 0ULL, sr23 = 0ULL, si23 = 0ULL;

    const float* zp = g_zt + (size_t)seq * LL + (size_t)c * CLEN;
    float*       yp = g_yt + (size_t)seq * LL + (size_t)c * CLEN;
    float dv = dcoef[h];
    bool first = (c == 0);

    for (int l0 = 0; l0 < CLEN; l0 += 16) {
        float zv = zp[l0 + ln];
        float c16[16];
        #pragma unroll
        for (int t = 0; t < 16; ++t) {
            float zb = __shfl_sync(0xffffffffu, zv, t, 16);
            ull z2 = pk2(zb, zb);
            ull t0 = fma2(an01, si01, z2);
            si01   = fma2(ai01, sr01, mul2(ar01, si01));
            sr01   = fma2(ar01, sr01, t0);
            ull t1 = fma2(an23, si23, z2);
            si23   = fma2(ai23, sr23, mul2(ar23, si23));
            sr23   = fma2(ar23, sr23, t1);
            ull av = fma2(wr01, sr01, mul2(wn01, si01));
            av = fma2(wr23, sr23, av);
            av = fma2(wn23, si23, av);
            float alo, ahi;
            upk2(av, alo, ahi);
            c16[t] = alo + ahi;
        }
        // reduce-scatter across 16 lanes: lane ln ends with sum for t=ln
        #pragma unroll
        for (int off = 8; off >= 1; off >>= 1) {
            bool up = (ln & off) != 0;
            #pragma unroll
            for (int j = 0; j < off; ++j) {
                float send = up ? c16[j] : c16[j + off];
                float keep = up ? c16[j + off] : c16[j];
                c16[j] = keep + __shfl_xor_sync(0xffffffffu, send, off, 16);
            }
        }
        float yv = fmaf(dv, zv, c16[0]);
        if (first) yv = gelu1(yv);
        yp[l0 + ln] = yv;
    }

    float4 vr, vi;
    upk2(sr01, vr.x, vr.y); upk2(sr23, vr.z, vr.w);
    upk2(si01, vi.x, vi.y); upk2(si23, vi.z, vi.w);
    size_t so = (size_t)unit * NN + ln * 4;
    *reinterpret_cast<float4*>(&g_esr[so]) = vr;
    *reinterpret_cast<float4*>(&g_esi[so]) = vi;
}

// ------------------------------------------------------------------
// Scan pass 2: correction for chunk 1, split into 2 sub-units of
// HALF=512 steps. Sub-unit 1 starts from dA^HALF * S.
// u_0 = w2 .* dA .* S_start, u_{t+1} = dA .* u_t; y += Re(sum u),
// then fused gelu.  2 sub-units/warp, 16 lanes each.
// ------------------------------------------------------------------
__global__ void __launch_bounds__(256, 4) scan2_kernel() {
    int warp = (blockIdx.x * blockDim.x + threadIdx.x) >> 5;
    int lane = threadIdx.x & 31;
    int half = lane >> 4;
    int ln   = lane & 15;
    int unit = warp * 2 + half;          // 0 .. B*H*2-1
    int seq  = unit >> 1;
    int sub  = unit & 1;
    int h = seq & 255;
    int base = h * NN + ln * 4;

    float a0r = g_ar[base+0], a1r = g_ar[base+1], a2r = g_ar[base+2], a3r = g_ar[base+3];
    float a0i = g_ai[base+0], a1i = g_ai[base+1], a2i = g_ai[base+2], a3i = g_ai[base+3];
    float w0r = g_wr[base+0], w1r = g_wr[base+1], w2r = g_wr[base+2], w3r = g_wr[base+3];
    float w0n = g_win[base+0], w1n = g_win[base+1], w2n = g_win[base+2], w3n = g_win[base+3];

    // S = end state of chunk 0 (stored at unit index seq*CH + 0)
    size_t eo = (size_t)(seq * CH) * NN + ln * 4;
    float4 e_r = *reinterpret_cast<const float4*>(&g_esr[eo]);
    float4 e_i = *reinterpret_cast<const float4*>(&g_esi[eo]);
    float Sr[4] = {e_r.x, e_r.y, e_r.z, e_r.w};
    float Si[4] = {e_i.x, e_i.y, e_i.z, e_i.w};

    if (sub) {   // advance start state by dA^HALF
        float4 p_r = *reinterpret_cast<const float4*>(&g_apr[base]);
        float4 p_i = *reinterpret_cast<const float4*>(&g_api[base]);
        float pr[4] = {p_r.x, p_r.y, p_r.z, p_r.w};
        float pi[4] = {p_i.x, p_i.y, p_i.z, p_i.w};
        #pragma unroll
        for (int q = 0; q < 4; ++q) {
            float nsr = pr[q] * Sr[q] - pi[q] * Si[q];
            float nsi = pr[q] * Si[q] + pi[q] * Sr[q];
            Sr[q] = nsr; Si[q] = nsi;
        }
    }

    ull ar01 = pk2(a0r, a1r), ar23 = pk2(a2r, a3r);
    ull ai01 = pk2(a0i, a1i), ai23 = pk2(a2i, a3i);
    ull an01 = pk2(-a0i, -a1i), an23 = pk2(-a2i, -a3i);

    ull sr01 = pk2(Sr[0], Sr[1]), sr23 = pk2(Sr[2], Sr[3]);
    ull si01 = pk2(Si[0], Si[1]), si23 = pk2(Si[2], Si[3]);

    // t = dA * S_start
    ull tr01 = fma2(ar01, sr01, mul2(an01, si01));
    ull ti01 = fma2(ai01, sr01, mul2(ar01, si01));
    ull tr23 = fma2(ar23, sr23, mul2(an23, si23));
    ull ti23 = fma2(ai23, sr23, mul2(ar23, si23));

    // u = w2 .* t   (Re(w2)=wr, Im(w2)=-wn)
    ull wr01 = pk2(w0r, w1r), wr23 = pk2(w2r, w3r);
    ull wn01 = pk2(w0n, w1n), wn23 = pk2(w2n, w3n);
    ull wm01 = pk2(-w0n, -w1n), wm23 = pk2(-w2n, -w3n);
    ull ur01 = fma2(wr01, tr01, mul2(wn01, ti01));
    ull ui01 = fma2(wr01, ti01, mul2(wm01, tr01));
    ull ur23 = fma2(wr23, tr23, mul2(wn23, ti23));
    ull ui23 = fma2(wr23, ti23, mul2(wm23, tr23));

    float* yp = g_yt + (size_t)seq * LL + CLEN + (size_t)sub * HALF;

    for (int l0 = 0; l0 < HALF; l0 += 16) {
        float c16[16];
        #pragma unroll
        for (int t = 0; t < 16; ++t) {
            ull sm = add2(ur01, ur23);
            float alo, ahi;
            upk2(sm, alo, ahi);
            c16[t] = alo + ahi;
            ull m0 = mul2(an01, ui01);
            ui01 = fma2(ai01, ur01, mul2(ar01, ui01));
            ur01 = fma2(ar01, ur01, m0);
            ull m1 = mul2(an23, ui23);
            ui23 = fma2(ai23, ur23, mul2(ar23, ui23));
            ur23 = fma2(ar23, ur23, m1);
        }
        #pragma unroll
        for (int off = 8; off >= 1; off >>= 1) {
            bool up = (ln & off) != 0;
            #pragma unroll
            for (int j = 0; j < off; ++j) {
                float send = up ? c16[j] : c16[j + off];
                float keep = up ? c16[j + off] : c16[j];
                c16[j] = keep + __shfl_xor_sync(0xffffffffu, send, off, 16);
            }
        }
        float yv = yp[l0 + ln] + c16[0];
        yp[l0 + ln] = gelu1(yv);
    }
}

// ------------------------------------------------------------------
// GLU GEMM via mma.sync tf32 (m16n8k8).  (unchanged from R5)
// ------------------------------------------------------------------
#define ASTR 136
#define BSTR 72
__global__ void __launch_bounds__(256) glu_gemm_mma(
        const float* __restrict__ W1, const float* __restrict__ W2,
        const float* __restrict__ b1, const float* __restrict__ b2) {
    __shared__ uint32_t As [32 * ASTR];   // [k][m], tf32
    __shared__ uint32_t Bs1[32 * BSTR];   // [k][n], tf32
    __shared__ uint32_t Bs2[32 * BSTR];

    int tid  = threadIdx.x;
    int wid  = tid >> 5;
    int lane = tid & 31;
    int g    = lane >> 2;
    int t    = lane & 3;
    int wm   = wid & 3;
    int wn   = wid >> 2;

    int m0  = blockIdx.x * 128;
    int n0  = blockIdx.y * 64;
    int bch = m0 >> 11;
    int ml0 = m0 & 2047;

    float acc1[2][4][4];
    float acc2[2][4][4];
    #pragma unroll
    for (int mi = 0; mi < 2; ++mi)
        #pragma unroll
        for (int nj = 0; nj < 4; ++nj)
            #pragma unroll
            for (int r = 0; r < 4; ++r) { acc1[mi][nj][r] = 0.f; acc2[mi][nj][r] = 0.f; }

    for (int kc = 0; kc < HH; kc += 32) {
        __syncthreads();
        #pragma unroll
        for (int it = 0; it < 4; ++it) {
            int item = it * 256 + tid;
            int krow = item >> 5;
            int c4   = (item & 31) * 4;
            const float* src = &g_yt[(size_t)(bch * HH + kc + krow) * LL + ml0 + c4];
            float4 v = *reinterpret_cast<const float4*>(src);
            uint32_t* dst = &As[krow * ASTR + c4];
            asm volatile("st.shared.v4.b32 [%0], {%1,%2,%3,%4};"
                :: "l"(dst), "r"(f2tf32(v.x)), "r"(f2tf32(v.y)),
                   "r"(f2tf32(v.z)), "r"(f2tf32(v.w)) : "memory");
        }
        #pragma unroll
        for (int it = 0; it < 2; ++it) {
            int item = it * 256 + tid;
            int gg = item & 63;
            int kq = item >> 6;
            size_t off = (size_t)(n0 + gg) * HH + kc + kq * 4;
            float4 w1 = *reinterpret_cast<const float4*>(&W1[off]);
            float4 w2 = *reinterpret_cast<const float4*>(&W2[off]);
            int kb = kq * 4;
            Bs1[(kb+0) * BSTR + gg] = f2tf32(w1.x);
            Bs1[(kb+1) * BSTR + gg] = f2tf32(w1.y);
            Bs1[(kb+2) * BSTR + gg] = f2tf32(w1.z);
            Bs1[(kb+3) * BSTR + gg] = f2tf32(w1.w);
            Bs2[(kb+0) * BSTR + gg] = f2tf32(w2.x);
            Bs2[(kb+1) * BSTR + gg] = f2tf32(w2.y);
            Bs2[(kb+2) * BSTR + gg] = f2tf32(w2.z);
            Bs2[(kb+3) * BSTR + gg] = f2tf32(w2.w);
        }
        __syncthreads();

        #pragma unroll
        for (int ks = 0; ks < 4; ++ks) {
            int kb = ks * 8;
            uint32_t af[2][4];
            #pragma unroll
            for (int mi = 0; mi < 2; ++mi) {
                int mrow = wm * 32 + mi * 16;
                af[mi][0] = As[(kb + t)     * ASTR + mrow + g];
                af[mi][1] = As[(kb + t)     * ASTR + mrow + g + 8];
                af[mi][2] = As[(kb + t + 4) * ASTR + mrow + g];
                af[mi][3] = As[(kb + t + 4) * ASTR + mrow + g + 8];
            }
            #pragma unroll
            for (int nj = 0; nj < 4; ++nj) {
                int ncol = wn * 32 + nj * 8 + g;
                uint32_t bA0 = Bs1[(kb + t)     * BSTR + ncol];
                uint32_t bA1 = Bs1[(kb + t + 4) * BSTR + ncol];
                uint32_t bB0 = Bs2[(kb + t)     * BSTR + ncol];
                uint32_t bB1 = Bs2[(kb + t + 4) * BSTR + ncol];
                #pragma unroll
                for (int mi = 0; mi < 2; ++mi) {
                    mma_tf32(acc1[mi][nj], af[mi][0], af[mi][1], af[mi][2], af[mi][3], bA0, bA1);
                    mma_tf32(acc2[mi][nj], af[mi][0], af[mi][1], af[mi][2], af[mi][3], bB0, bB1);
                }
            }
        }
    }

    #pragma unroll
    for (int nj = 0; nj < 4; ++nj) {
        int ncol = n0 + wn * 32 + nj * 8 + t * 2;
        float bb1a = b1[ncol], bb1b = b1[ncol + 1];
        float bb2a = b2[ncol], bb2b = b2[ncol + 1];
        #pragma unroll
        for (int mi = 0; mi < 2; ++mi) {
            #pragma unroll
            for (int rr = 0; rr < 2; ++rr) {
                int mrow = m0 + wm * 32 + mi * 16 + g + rr * 8;
                float* hp = &g_h[(size_t)mrow * HH + ncol];
                float2 hv = *reinterpret_cast<float2*>(hp);
                float d1a = acc1[mi][nj][rr * 2 + 0] + bb1a;
                float d1b = acc1[mi][nj][rr * 2 + 1] + bb1b;
                float d2a = acc2[mi][nj][rr * 2 + 0] + bb2a;
                float d2b = acc2[mi][nj][rr * 2 + 1] + bb2b;
                hv.x += d1a * (1.0f / (1.0f + expf(-d2a)));
                hv.y += d1b * (1.0f / (1.0f + expf(-d2b)));
                *reinterpret_cast<float2*>(hp) = hv;
            }
        }
    }
}

// ------------------------------------------------------------------
// Decoder
// ------------------------------------------------------------------
__global__ void dec_kernel(const float* __restrict__ dw,
                           const float* __restrict__ db,
                           float* __restrict__ out) {
    int warp = (blockIdx.x * blockDim.x + threadIdx.x) >> 5;
    int lane = threadIdx.x & 31;
    const float* row = g_h + (size_t)warp * HH;
    float hr[8];
    #pragma unroll
    for (int k = 0; k < 8; ++k) hr[k] = row[lane + 32 * k];
    for (int o = 0; o < OUTD; ++o) {
        const float* wrow = dw + o * HH + lane;
        float acc = 0.0f;
        #pragma unroll
        for (int k = 0; k < 8; ++k) acc = fmaf(hr[k], wrow[32 * k], acc);
        #pragma unroll
        for (int m = 16; m; m >>= 1) acc += __shfl_xor_sync(0xffffffffu, acc, m);
        if (lane == 0) out[(size_t)warp * OUTD + o] = acc + db[o];
    }
}

// ------------------------------------------------------------------
extern "C" void kernel_launch(void* const* d_in, const int* in_sizes, int n_in,
                              void* d_out, int out_size) {
    const float* x     = (const float*)d_in[0];
    const float* enc_w = (const float*)d_in[1];
    const float* enc_b = (const float*)d_in[2];
    const float* lre   = (const float*)d_in[3];
    const float* lim   = (const float*)d_in[4];
    const float* cre   = (const float*)d_in[5];
    const float* cim   = (const float*)d_in[6];
    const float* dd    = (const float*)d_in[7];
    const float* lstep = (const float*)d_in[8];
    const float* lns   = (const float*)d_in[9];
    const float* lnb   = (const float*)d_in[10];
    const float* ow    = (const float*)d_in[11];
    const float* ob    = (const float*)d_in[12];
    const float* o2w   = (const float*)d_in[13];
    const float* o2b   = (const float*)d_in[14];
    const float* dw    = (const float*)d_in[15];
    const float* db    = (const float*)d_in[16];
    float* out = (float*)d_out;

    enc_kernel<<<(BB * LL) / 16, 256>>>(x, enc_w, enc_b);

    for (int li = 0; li < NLAY; ++li) {
        ln_kernel<<<(BB * LL) / 32, 256>>>(lns + li * HH, lnb + li * HH);
        ssm_params_kernel<<<(HH * NN) / 256, 256>>>(
            lre + li * HH * NN, lim + li * HH * NN,
            cre + li * HH * NN, cim + li * HH * NN, lstep + li * HH);
        // scan1: B*H*CH units, 2/warp, 8 warps/block
        scan1_kernel<<<(BB * HH * CH) / 16, 256>>>(dd + li * HH);
        // scan2: B*H*2 sub-units, 2/warp
        scan2_kernel<<<(BB * HH * 2) / 16, 256>>>();
        glu_gemm_mma<<<dim3((BB * LL) / 128, HH / 64), 256>>>(
            ow + li * HH * HH, o2w + li * HH * HH,
            ob + li * HH, o2b + li * HH);
    }

    dec_kernel<<<(BB * LL) / 8, 256>>>(dw, db, out);
}

// round 9
// speedup vs baseline: 1.5879x; 1.5879x over previous
#include <cuda_runtime.h>
#include <math.h>
#include <stdint.h>

// Problem dims (fixed)
#define BB   16
#define LL   2048
#define HH   256
#define NN   64
#define NLAY 4
#define IND  40
#define OUTD 33

// Chunked-scan config: 2 chunks of 1024; scan2 sub-splits into 512-step units
#define CH    2
#define CLEN  1024
#define HALF  512

typedef unsigned long long ull;

// ------------------------------------------------------------------
// Scratch (device globals)
// ------------------------------------------------------------------
__device__ float g_h[BB * LL * HH];   // residual stream, [m][h]
__device__ float g_zt[BB * HH * LL];  // layernorm output, TRANSPOSED [seq][l]
__device__ float g_yt[BB * HH * LL];  // SSM/gelu output, TRANSPOSED [seq][l]
__device__ float g_ar[HH * NN];
__device__ float g_ai[HH * NN];
__device__ float g_wr[HH * NN];
__device__ float g_win[HH * NN];
__device__ float g_apr[HH * NN];      // Re(dA^HALF)
__device__ float g_api[HH * NN];      // Im(dA^HALF)
__device__ float g_esr[BB * HH * CH * NN];
__device__ float g_esi[BB * HH * CH * NN];

// ------------------------------------------------------------------
// f32x2 packed math (Blackwell)
// ------------------------------------------------------------------
__device__ __forceinline__ ull pk2(float lo, float hi) {
    ull r;
    asm("mov.b64 %0, {%1, %2};" : "=l"(r) : "f"(lo), "f"(hi));
    return r;
}
__device__ __forceinline__ void upk2(ull v, float& lo, float& hi) {
    asm("mov.b64 {%0, %1}, %2;" : "=f"(lo), "=f"(hi) : "l"(v));
}
__device__ __forceinline__ ull fma2(ull a, ull b, ull c) {
    ull d;
    asm("fma.rn.f32x2 %0, %1, %2, %3;" : "=l"(d) : "l"(a), "l"(b), "l"(c));
    return d;
}
__device__ __forceinline__ ull mul2(ull a, ull b) {
    ull d;
    asm("mul.rn.f32x2 %0, %1, %2;" : "=l"(d) : "l"(a), "l"(b));
    return d;
}
__device__ __forceinline__ ull add2(ull a, ull b) {
    ull d;
    asm("add.rn.f32x2 %0, %1, %2;" : "=l"(d) : "l"(a), "l"(b));
    return d;
}

__device__ __forceinline__ float gelu1(float x) {
    const float c0 = 0.7978845608028654f;
    const float c1 = 0.044715f;
    float t = tanhf(c0 * (x + c1 * x * x * x));
    return 0.5f * x * (1.0f + t);
}

__device__ __forceinline__ uint32_t f2tf32(float x) {
    uint32_t r;
    asm("cvt.rna.tf32.f32 %0, %1;" : "=r"(r) : "f"(x));
    return r;
}

// mma.sync tf32 m16n8k8 (sm_80+, valid on target sm_103)
__device__ __forceinline__ void mma_tf32(float c[4],
                                         uint32_t a0, uint32_t a1,
                                         uint32_t a2, uint32_t a3,
                                         uint32_t b0, uint32_t b1) {
    asm volatile(
        "mma.sync.aligned.m16n8k8.row.col.f32.tf32.tf32.f32 "
        "{%0,%1,%2,%3}, {%4,%5,%6,%7}, {%8,%9}, {%0,%1,%2,%3};"
        : "+f"(c[0]), "+f"(c[1]), "+f"(c[2]), "+f"(c[3])
        : "r"(a0), "r"(a1), "r"(a2), "r"(a3), "r"(b0), "r"(b1));
}

// ------------------------------------------------------------------
// Encoder
// ------------------------------------------------------------------
__global__ void enc_kernel(const float* __restrict__ x,
                           const float* __restrict__ ew,
                           const float* __restrict__ eb) {
    __shared__ float sw[IND * HH];
    __shared__ float sx[16 * IND];
    int tid = threadIdx.x;
    for (int idx = tid; idx < HH * IND; idx += 256) {
        int h = idx / IND, i = idx % IND;
        sw[i * HH + h] = ew[idx];
    }
    int m0 = blockIdx.x * 16;
    for (int idx = tid; idx < 16 * IND; idx += 256)
        sx[idx] = x[(size_t)m0 * IND + idx];
    __syncthreads();
    float bias = eb[tid];
    for (int r = 0; r < 16; ++r) {
        float acc = bias;
        #pragma unroll
        for (int i = 0; i < IND; ++i)
            acc = fmaf(sx[r * IND + i], sw[i * HH + tid], acc);
        g_h[(size_t)(m0 + r) * HH + tid] = acc;
    }
}

// ------------------------------------------------------------------
// LayerNorm + transpose
// ------------------------------------------------------------------
__global__ void ln_kernel(const float* __restrict__ sc,
                          const float* __restrict__ bi) {
    __shared__ float sm[32][257];
    int tid  = threadIdx.x;
    int warp = tid >> 5;
    int lane = tid & 31;
    int m0 = blockIdx.x * 32;

    for (int r = warp; r < 32; r += 8) {
        const float* row = g_h + (size_t)(m0 + r) * HH;
        float4 v0 = *reinterpret_cast<const float4*>(row + lane * 4);
        float4 v1 = *reinterpret_cast<const float4*>(row + 128 + lane * 4);
        float s = v0.x + v0.y + v0.z + v0.w + v1.x + v1.y + v1.z + v1.w;
        float q = v0.x*v0.x + v0.y*v0.y + v0.z*v0.z + v0.w*v0.w
                + v1.x*v1.x + v1.y*v1.y + v1.z*v1.z + v1.w*v1.w;
        #pragma unroll
        for (int m = 16; m; m >>= 1) {
            s += __shfl_xor_sync(0xffffffffu, s, m);
            q += __shfl_xor_sync(0xffffffffu, q, m);
        }
        float mu  = s * (1.0f / 256.0f);
        float var = q * (1.0f / 256.0f) - mu * mu;
        float inv = rsqrtf(var + 1e-5f);
        int h0 = lane * 4, h1 = 128 + lane * 4;
        sm[r][h0+0] = (v0.x - mu) * inv * sc[h0+0] + bi[h0+0];
        sm[r][h0+1] = (v0.y - mu) * inv * sc[h0+1] + bi[h0+1];
        sm[r][h0+2] = (v0.z - mu) * inv * sc[h0+2] + bi[h0+2];
        sm[r][h0+3] = (v0.w - mu) * inv * sc[h0+3] + bi[h0+3];
        sm[r][h1+0] = (v1.x - mu) * inv * sc[h1+0] + bi[h1+0];
        sm[r][h1+1] = (v1.y - mu) * inv * sc[h1+1] + bi[h1+1];
        sm[r][h1+2] = (v1.z - mu) * inv * sc[h1+2] + bi[h1+2];
        sm[r][h1+3] = (v1.w - mu) * inv * sc[h1+3] + bi[h1+3];
    }
    __syncthreads();

    int b  = m0 >> 11;
    int l0 = m0 & 2047;
    for (int h = warp; h < HH; h += 8) {
        g_zt[((size_t)(b * HH + h)) * LL + l0 + lane] = sm[lane][h];
    }
}

// ------------------------------------------------------------------
// S4D discretization + dA^HALF (double)
// ------------------------------------------------------------------
__global__ void ssm_params_kernel(const float* __restrict__ lre,
                                  const float* __restrict__ lim,
                                  const float* __restrict__ cre,
                                  const float* __restrict__ cim,
                                  const float* __restrict__ lstep) {
    int idx = blockIdx.x * blockDim.x + threadIdx.x;
    if (idx >= HH * NN) return;
    int h = idx >> 6;
    float Lre = lre[idx], Lim = lim[idx];
    float Cre = cre[idx], Cim = cim[idx];
    float dt  = expf(lstep[h]);
    float mag = expf(Lre * dt);
    float th  = Lim * dt;
    float dar = mag * cosf(th);
    float dai = mag * sinf(th);
    float den = Lre * Lre + Lim * Lim;
    float nr = dar - 1.0f, ni = dai;
    float dbr = (nr * Lre + ni * Lim) / den;
    float dbi = (ni * Lre - nr * Lim) / den;
    float wr = Cre * dbr - Cim * dbi;
    float wi = Cre * dbi + Cim * dbr;
    g_ar[idx]  = dar;
    g_ai[idx]  = dai;
    g_wr[idx]  = 2.0f * wr;
    g_win[idx] = -2.0f * wi;
    double dtd = exp((double)lstep[h]);
    double mr  = exp((double)Lre * dtd * (double)HALF);
    double thd = (double)Lim * dtd * (double)HALF;
    g_apr[idx] = (float)(mr * cos(thd));
    g_api[idx] = (float)(mr * sin(thd));
}

// ------------------------------------------------------------------
// Scan pass 1 (R5 configuration): 2 units/warp, 16 lanes/unit,
// 4 complex states/lane, 16-step tiles + reduce-scatter,
// fused gelu on chunk 0.  CH=2, CLEN=1024.
// ------------------------------------------------------------------
__global__ void __launch_bounds__(256, 4) scan1_kernel(const float* __restrict__ dcoef) {
    int warp = (blockIdx.x * blockDim.x + threadIdx.x) >> 5;
    int lane = threadIdx.x & 31;
    int half = lane >> 4;
    int ln   = lane & 15;
    int unit = warp * 2 + half;        // 0..B*H*CH-1
    int seq  = unit >> 1;              // unit / CH
    int c    = unit & (CH - 1);
    int h = seq & 255;
    int base = h * NN + ln * 4;

    float a0r = g_ar[base+0], a1r = g_ar[base+1], a2r = g_ar[base+2], a3r = g_ar[base+3];
    float a0i = g_ai[base+0], a1i = g_ai[base+1], a2i = g_ai[base+2], a3i = g_ai[base+3];
    float w0r = g_wr[base+0], w1r = g_wr[base+1], w2r = g_wr[base+2], w3r = g_wr[base+3];
    float w0n = g_win[base+0], w1n = g_win[base+1], w2n = g_win[base+2], w3n = g_win[base+3];

    ull ar01 = pk2(a0r, a1r), ar23 = pk2(a2r, a3r);
    ull ai01 = pk2(a0i, a1i), ai23 = pk2(a2i, a3i);
    ull an01 = pk2(-a0i, -a1i), an23 = pk2(-a2i, -a3i);
    ull wr01 = pk2(w0r, w1r), wr23 = pk2(w2r, w3r);
    ull wn01 = pk2(w0n, w1n), wn23 = pk2(w2n, w3n);

    ull sr01 = 0ULL, si01 = 0ULL, sr23 = 0ULL, si23 = 0ULL;

    const float* zp = g_zt + (size_t)seq * LL + (size_t)c * CLEN;
    float*       yp = g_yt + (size_t)seq * LL + (size_t)c * CLEN;
    float dv = dcoef[h];
    bool first = (c == 0);

    for (int l0 = 0; l0 < CLEN; l0 += 16) {
        float zv = zp[l0 + ln];
        float c16[16];
        #pragma unroll
        for (int t = 0; t < 16; ++t) {
            float zb = __shfl_sync(0xffffffffu, zv, t, 16);
            ull z2 = pk2(zb, zb);
            ull t0 = fma2(an01, si01, z2);
            si01   = fma2(ai01, sr01, mul2(ar01, si01));
            sr01   = fma2(ar01, sr01, t0);
            ull t1 = fma2(an23, si23, z2);
            si23   = fma2(ai23, sr23, mul2(ar23, si23));
            sr23   = fma2(ar23, sr23, t1);
            ull av = fma2(wr01, sr01, mul2(wn01, si01));
            av = fma2(wr23, sr23, av);
            av = fma2(wn23, si23, av);
            float alo, ahi;
            upk2(av, alo, ahi);
            c16[t] = alo + ahi;
        }
        // reduce-scatter across 16 lanes: lane ln ends with sum for t=ln
        #pragma unroll
        for (int off = 8; off >= 1; off >>= 1) {
            bool up = (ln & off) != 0;
            #pragma unroll
            for (int j = 0; j < off; ++j) {
                float send = up ? c16[j] : c16[j + off];
                float keep = up ? c16[j + off] : c16[j];
                c16[j] = keep + __shfl_xor_sync(0xffffffffu, send, off, 16);
            }
        }
        float yv = fmaf(dv, zv, c16[0]);
        if (first) yv = gelu1(yv);
        yp[l0 + ln] = yv;
    }

    float4 vr, vi;
    upk2(sr01, vr.x, vr.y); upk2(sr23, vr.z, vr.w);
    upk2(si01, vi.x, vi.y); upk2(si23, vi.z, vi.w);
    size_t so = (size_t)unit * NN + ln * 4;
    *reinterpret_cast<float4*>(&g_esr[so]) = vr;
    *reinterpret_cast<float4*>(&g_esi[so]) = vi;
}

// ------------------------------------------------------------------
// Scan pass 2: correction for chunk 1, split into 2 sub-units of
// HALF=512 steps. Sub-unit 1 starts from dA^HALF * S.
// u_0 = w2 .* dA .* S_start, u_{t+1} = dA .* u_t; y += Re(sum u),
// then fused gelu.  2 sub-units/warp, 16 lanes each.
// ------------------------------------------------------------------
__global__ void __launch_bounds__(256, 4) scan2_kernel() {
    int warp = (blockIdx.x * blockDim.x + threadIdx.x) >> 5;
    int lane = threadIdx.x & 31;
    int half = lane >> 4;
    int ln   = lane & 15;
    int unit = warp * 2 + half;          // 0 .. B*H*2-1
    int seq  = unit >> 1;
    int sub  = unit & 1;
    int h = seq & 255;
    int base = h * NN + ln * 4;

    float a0r = g_ar[base+0], a1r = g_ar[base+1], a2r = g_ar[base+2], a3r = g_ar[base+3];
    float a0i = g_ai[base+0], a1i = g_ai[base+1], a2i = g_ai[base+2], a3i = g_ai[base+3];
    float w0r = g_wr[base+0], w1r = g_wr[base+1], w2r = g_wr[base+2], w3r = g_wr[base+3];
    float w0n = g_win[base+0], w1n = g_win[base+1], w2n = g_win[base+2], w3n = g_win[base+3];

    // S = end state of chunk 0 (stored at unit index seq*CH + 0)
    size_t eo = (size_t)(seq * CH) * NN + ln * 4;
    float4 e_r = *reinterpret_cast<const float4*>(&g_esr[eo]);
    float4 e_i = *reinterpret_cast<const float4*>(&g_esi[eo]);
    float Sr[4] = {e_r.x, e_r.y, e_r.z, e_r.w};
    float Si[4] = {e_i.x, e_i.y, e_i.z, e_i.w};

    if (sub) {   // advance start state by dA^HALF
        float4 p_r = *reinterpret_cast<const float4*>(&g_apr[base]);
        float4 p_i = *reinterpret_cast<const float4*>(&g_api[base]);
        float pr[4] = {p_r.x, p_r.y, p_r.z, p_r.w};
        float pi[4] = {p_i.x, p_i.y, p_i.z, p_i.w};
        #pragma unroll
        for (int q = 0; q < 4; ++q) {
            float nsr = pr[q] * Sr[q] - pi[q] * Si[q];
            float nsi = pr[q] * Si[q] + pi[q] * Sr[q];
            Sr[q] = nsr; Si[q] = nsi;
        }
    }

    ull ar01 = pk2(a0r, a1r), ar23 = pk2(a2r, a3r);
    ull ai01 = pk2(a0i, a1i), ai23 = pk2(a2i, a3i);
    ull an01 = pk2(-a0i, -a1i), an23 = pk2(-a2i, -a3i);

    ull sr01 = pk2(Sr[0], Sr[1]), sr23 = pk2(Sr[2], Sr[3]);
    ull si01 = pk2(Si[0], Si[1]), si23 = pk2(Si[2], Si[3]);

    // t = dA * S_start
    ull tr01 = fma2(ar01, sr01, mul2(an01, si01));
    ull ti01 = fma2(ai01, sr01, mul2(ar01, si01));
    ull tr23 = fma2(ar23, sr23, mul2(an23, si23));
    ull ti23 = fma2(ai23, sr23, mul2(ar23, si23));

    // u = w2 .* t   (Re(w2)=wr, Im(w2)=-wn)
    ull wr01 = pk2(w0r, w1r), wr23 = pk2(w2r, w3r);
    ull wn01 = pk2(w0n, w1n), wn23 = pk2(w2n, w3n);
    ull wm01 = pk2(-w0n, -w1n), wm23 = pk2(-w2n, -w3n);
    ull ur01 = fma2(wr01, tr01, mul2(wn01, ti01));
    ull ui01 = fma2(wr01, ti01, mul2(wm01, tr01));
    ull ur23 = fma2(wr23, tr23, mul2(wn23, ti23));
    ull ui23 = fma2(wr23, ti23, mul2(wm23, tr23));

    float* yp = g_yt + (size_t)seq * LL + CLEN + (size_t)sub * HALF;

    for (int l0 = 0; l0 < HALF; l0 += 16) {
        float c16[16];
        #pragma unroll
        for (int t = 0; t < 16; ++t) {
            ull sm = add2(ur01, ur23);
            float alo, ahi;
            upk2(sm, alo, ahi);
            c16[t] = alo + ahi;
            ull m0 = mul2(an01, ui01);
            ui01 = fma2(ai01, ur01, mul2(ar01, ui01));
            ur01 = fma2(ar01, ur01, m0);
            ull m1 = mul2(an23, ui23);
            ui23 = fma2(ai23, ur23, mul2(ar23, ui23));
            ur23 = fma2(ar23, ur23, m1);
        }
        #pragma unroll
        for (int off = 8; off >= 1; off >>= 1) {
            bool up = (ln & off) != 0;
            #pragma unroll
            for (int j = 0; j < off; ++j) {
                float send = up ? c16[j] : c16[j + off];
                float keep = up ? c16[j + off] : c16[j];
                c16[j] = keep + __shfl_xor_sync(0xffffffffu, send, off, 16);
            }
        }
        float yv = yp[l0 + ln] + c16[0];
        yp[l0 + ln] = gelu1(yv);
    }
}

// ------------------------------------------------------------------
// GLU GEMM via mma.sync tf32 (m16n8k8).  (unchanged from R5)
// ------------------------------------------------------------------
#define ASTR 136
#define BSTR 72
__global__ void __launch_bounds__(256) glu_gemm_mma(
        const float* __restrict__ W1, const float* __restrict__ W2,
        const float* __restrict__ b1, const float* __restrict__ b2) {
    __shared__ uint32_t As [32 * ASTR];   // [k][m], tf32
    __shared__ uint32_t Bs1[32 * BSTR];   // [k][n], tf32
    __shared__ uint32_t Bs2[32 * BSTR];

    int tid  = threadIdx.x;
    int wid  = tid >> 5;
    int lane = tid & 31;
    int g    = lane >> 2;
    int t    = lane & 3;
    int wm   = wid & 3;
    int wn   = wid >> 2;

    int m0  = blockIdx.x * 128;
    int n0  = blockIdx.y * 64;
    int bch = m0 >> 11;
    int ml0 = m0 & 2047;

    float acc1[2][4][4];
    float acc2[2][4][4];
    #pragma unroll
    for (int mi = 0; mi < 2; ++mi)
        #pragma unroll
        for (int nj = 0; nj < 4; ++nj)
            #pragma unroll
            for (int r = 0; r < 4; ++r) { acc1[mi][nj][r] = 0.f; acc2[mi][nj][r] = 0.f; }

    for (int kc = 0; kc < HH; kc += 32) {
        __syncthreads();
        #pragma unroll
        for (int it = 0; it < 4; ++it) {
            int item = it * 256 + tid;
            int krow = item >> 5;
            int c4   = (item & 31) * 4;
            const float* src = &g_yt[(size_t)(bch * HH + kc + krow) * LL + ml0 + c4];
            float4 v = *reinterpret_cast<const float4*>(src);
            uint32_t* dst = &As[krow * ASTR + c4];
            asm volatile("st.shared.v4.b32 [%0], {%1,%2,%3,%4};"
                :: "l"(dst), "r"(f2tf32(v.x)), "r"(f2tf32(v.y)),
                   "r"(f2tf32(v.z)), "r"(f2tf32(v.w)) : "memory");
        }
        #pragma unroll
        for (int it = 0; it < 2; ++it) {
            int item = it * 256 + tid;
            int gg = item & 63;
            int kq = item >> 6;
            size_t off = (size_t)(n0 + gg) * HH + kc + kq * 4;
            float4 w1 = *reinterpret_cast<const float4*>(&W1[off]);
            float4 w2 = *reinterpret_cast<const float4*>(&W2[off]);
            int kb = kq * 4;
            Bs1[(kb+0) * BSTR + gg] = f2tf32(w1.x);
            Bs1[(kb+1) * BSTR + gg] = f2tf32(w1.y);
            Bs1[(kb+2) * BSTR + gg] = f2tf32(w1.z);
            Bs1[(kb+3) * BSTR + gg] = f2tf32(w1.w);
            Bs2[(kb+0) * BSTR + gg] = f2tf32(w2.x);
            Bs2[(kb+1) * BSTR + gg] = f2tf32(w2.y);
            Bs2[(kb+2) * BSTR + gg] = f2tf32(w2.z);
            Bs2[(kb+3) * BSTR + gg] = f2tf32(w2.w);
        }
        __syncthreads();

        #pragma unroll
        for (int ks = 0; ks < 4; ++ks) {
            int kb = ks * 8;
            uint32_t af[2][4];
            #pragma unroll
            for (int mi = 0; mi < 2; ++mi) {
                int mrow = wm * 32 + mi * 16;
                af[mi][0] = As[(kb + t)     * ASTR + mrow + g];
                af[mi][1] = As[(kb + t)     * ASTR + mrow + g + 8];
                af[mi][2] = As[(kb + t + 4) * ASTR + mrow + g];
                af[mi][3] = As[(kb + t + 4) * ASTR + mrow + g + 8];
            }
            #pragma unroll
            for (int nj = 0; nj < 4; ++nj) {
                int ncol = wn * 32 + nj * 8 + g;
                uint32_t bA0 = Bs1[(kb + t)     * BSTR + ncol];
                uint32_t bA1 = Bs1[(kb + t + 4) * BSTR + ncol];
                uint32_t bB0 = Bs2[(kb + t)     * BSTR + ncol];
                uint32_t bB1 = Bs2[(kb + t + 4) * BSTR + ncol];
                #pragma unroll
                for (int mi = 0; mi < 2; ++mi) {
                    mma_tf32(acc1[mi][nj], af[mi][0], af[mi][1], af[mi][2], af[mi][3], bA0, bA1);
                    mma_tf32(acc2[mi][nj], af[mi][0], af[mi][1], af[mi][2], af[mi][3], bB0, bB1);
                }
            }
        }
    }

    #pragma unroll
    for (int nj = 0; nj < 4; ++nj) {
        int ncol = n0 + wn * 32 + nj * 8 + t * 2;
        float bb1a = b1[ncol], bb1b = b1[ncol + 1];
        float bb2a = b2[ncol], bb2b = b2[ncol + 1];
        #pragma unroll
        for (int mi = 0; mi < 2; ++mi) {
            #pragma unroll
            for (int rr = 0; rr < 2; ++rr) {
                int mrow = m0 + wm * 32 + mi * 16 + g + rr * 8;
                float* hp = &g_h[(size_t)mrow * HH + ncol];
                float2 hv = *reinterpret_cast<float2*>(hp);
                float d1a = acc1[mi][nj][rr * 2 + 0] + bb1a;
                float d1b = acc1[mi][nj][rr * 2 + 1] + bb1b;
                float d2a = acc2[mi][nj][rr * 2 + 0] + bb2a;
                float d2b = acc2[mi][nj][rr * 2 + 1] + bb2b;
                hv.x += d1a * (1.0f / (1.0f + expf(-d2a)));
                hv.y += d1b * (1.0f / (1.0f + expf(-d2b)));
                *reinterpret_cast<float2*>(hp) = hv;
            }
        }
    }
}

// ------------------------------------------------------------------
// Decoder
// ------------------------------------------------------------------
__global__ void dec_kernel(const float* __restrict__ dw,
                           const float* __restrict__ db,
                           float* __restrict__ out) {
    int warp = (blockIdx.x * blockDim.x + threadIdx.x) >> 5;
    int lane = threadIdx.x & 31;
    const float* row = g_h + (size_t)warp * HH;
    float hr[8];
    #pragma unroll
    for (int k = 0; k < 8; ++k) hr[k] = row[lane + 32 * k];
    for (int o = 0; o < OUTD; ++o) {
        const float* wrow = dw + o * HH + lane;
        float acc = 0.0f;
        #pragma unroll
        for (int k = 0; k < 8; ++k) acc = fmaf(hr[k], wrow[32 * k], acc);
        #pragma unroll
        for (int m = 16; m; m >>= 1) acc += __shfl_xor_sync(0xffffffffu, acc, m);
        if (lane == 0) out[(size_t)warp * OUTD + o] = acc + db[o];
    }
}

// ------------------------------------------------------------------
extern "C" void kernel_launch(void* const* d_in, const int* in_sizes, int n_in,
                              void* d_out, int out_size) {
    const float* x     = (const float*)d_in[0];
    const float* enc_w = (const float*)d_in[1];
    const float* enc_b = (const float*)d_in[2];
    const float* lre   = (const float*)d_in[3];
    const float* lim   = (const float*)d_in[4];
    const float* cre   = (const float*)d_in[5];
    const float* cim   = (const float*)d_in[6];
    const float* dd    = (const float*)d_in[7];
    const float* lstep = (const float*)d_in[8];
    const float* lns   = (const float*)d_in[9];
    const float* lnb   = (const float*)d_in[10];
    const float* ow    = (const float*)d_in[11];
    const float* ob    = (const float*)d_in[12];
    const float* o2w   = (const float*)d_in[13];
    const float* o2b   = (const float*)d_in[14];
    const float* dw    = (const float*)d_in[15];
    const float* db    = (const float*)d_in[16];
    float* out = (float*)d_out;

    enc_kernel<<<(BB * LL) / 16, 256>>>(x, enc_w, enc_b);

    for (int li = 0; li < NLAY; ++li) {
        ln_kernel<<<(BB * LL) / 32, 256>>>(lns + li * HH, lnb + li * HH);
        ssm_params_kernel<<<(HH * NN) / 256, 256>>>(
            lre + li * HH * NN, lim + li * HH * NN,
            cre + li * HH * NN, cim + li * HH * NN, lstep + li * HH);
        // scan1: B*H*CH units, 2/warp, 8 warps/block
        scan1_kernel<<<(BB * HH * CH) / 16, 256>>>(dd + li * HH);
        // scan2: B*H*2 sub-units, 2/warp
        scan2_kernel<<<(BB * HH * 2) / 16, 256>>>();
        glu_gemm_mma<<<dim3((BB * LL) / 128, HH / 64), 256>>>(
            ow + li * HH * HH, o2w + li * HH * HH,
            ob + li * HH, o2b + li * HH);
    }

    dec_kernel<<<(BB * LL) / 8, 256>>>(dw, db, out);
}

// round 10
// speedup vs baseline: 2.1654x; 1.3636x over previous
#include <cuda_runtime.h>
#include <cuda_bf16.h>
#include <math.h>
#include <stdint.h>

#define BB   16
#define LL   2048
#define HH   256
#define NN   64
#define NLAY 4
#define IND  40
#define OUTD 33
#define TB   64
#define NBLK 32

typedef unsigned long long ull;

__device__ float g_h [BB * LL * HH];
__device__ float g_zt[BB * HH * LL];
__device__ float g_yt[BB * HH * LL];
__device__ float g_ar [HH * NN], g_ai [HH * NN];
__device__ float g_w2r[HH * NN], g_w2i[HH * NN];
__device__ float g_aTr[HH * NN], g_aTi[HH * NN];
__device__ float g_pr [HH * TB * NN], g_pi [HH * TB * NN];
__device__ float g_kv [HH * TB];
__device__ uint32_t g_bl_hi[HH * 32 * 192], g_bl_lo[HH * 32 * 192];
__device__ uint32_t g_bc_hi[HH * 64 * 64],  g_bc_lo[HH * 64 * 64];

__device__ __forceinline__ float gelu1(float x) {
    const float c0 = 0.7978845608028654f, c1 = 0.044715f;
    float t = tanhf(c0 * (x + c1 * x * x * x));
    return 0.5f * x * (1.0f + t);
}
__device__ __forceinline__ uint32_t f2tf32(float x) {
    uint32_t r; asm("cvt.rna.tf32.f32 %0, %1;" : "=r"(r) : "f"(x)); return r;
}
__device__ __forceinline__ uint32_t pkbf(float a, float b) {
    __nv_bfloat162 v = __floats2bfloat162_rn(a, b);
    return *reinterpret_cast<uint32_t*>(&v);
}
__device__ __forceinline__ void bsplit(float x, float& hi, float& lo) {
    float hf = __bfloat162float(__float2bfloat16(x));
    hi = hf; lo = x - hf;
}
__device__ __forceinline__ void mma_tf32(float c[4], uint32_t a0, uint32_t a1,
                                         uint32_t a2, uint32_t a3,
                                         uint32_t b0, uint32_t b1) {
    asm volatile("mma.sync.aligned.m16n8k8.row.col.f32.tf32.tf32.f32 "
        "{%0,%1,%2,%3}, {%4,%5,%6,%7}, {%8,%9}, {%0,%1,%2,%3};"
        : "+f"(c[0]), "+f"(c[1]), "+f"(c[2]), "+f"(c[3])
        : "r"(a0), "r"(a1), "r"(a2), "r"(a3), "r"(b0), "r"(b1));
}
__device__ __forceinline__ void mma_bf16(float c[4], uint32_t a0, uint32_t a1,
                                         uint32_t a2, uint32_t a3,
                                         uint32_t b0, uint32_t b1) {
    asm volatile("mma.sync.aligned.m16n8k16.row.col.f32.bf16.bf16.f32 "
        "{%0,%1,%2,%3}, {%4,%5,%6,%7}, {%8,%9}, {%0,%1,%2,%3};"
        : "+f"(c[0]), "+f"(c[1]), "+f"(c[2]), "+f"(c[3])
        : "r"(a0), "r"(a1), "r"(a2), "r"(a3), "r"(b0), "r"(b1));
}

__global__ void enc_kernel(const float* __restrict__ x,
                           const float* __restrict__ ew,
                           const float* __restrict__ eb) {
    __shared__ float sw[IND * HH];
    __shared__ float sx[16 * IND];
    int tid = threadIdx.x;
    for (int idx = tid; idx < HH * IND; idx += 256) {
        int h = idx / IND, i = idx % IND;
        sw[i * HH + h] = ew[idx];
    }
    int m0 = blockIdx.x * 16;
    for (int idx = tid; idx < 16 * IND; idx += 256)
        sx[idx] = x[(size_t)m0 * IND + idx];
    __syncthreads();
    float bias = eb[tid];
    for (int r = 0; r < 16; ++r) {
        float acc = bias;
        #pragma unroll
        for (int i = 0; i < IND; ++i)
            acc = fmaf(sx[r * IND + i], sw[i * HH + tid], acc);
        g_h[(size_t)(m0 + r) * HH + tid] = acc;
    }
}

__global__ void ln_kernel(const float* __restrict__ sc,
                          const float* __restrict__ bi) {
    __shared__ float sm[32][257];
    int tid  = threadIdx.x;
    int warp = tid >> 5;
    int lane = tid & 31;
    int m0 = blockIdx.x * 32;
    for (int r = warp; r < 32; r += 8) {
        const float* row = g_h + (size_t)(m0 + r) * HH;
        float4 v0 = *reinterpret_cast<const float4*>(row + lane * 4);
        float4 v1 = *reinterpret_cast<const float4*>(row + 128 + lane * 4);
        float s = v0.x + v0.y + v0.z + v0.w + v1.x + v1.y + v1.z + v1.w;
        float q = v0.x*v0.x + v0.y*v0.y + v0.z*v0.z + v0.w*v0.w
                + v1.x*v1.x + v1.y*v1.y + v1.z*v1.z + v1.w*v1.w;
        #pragma unroll
        for (int m = 16; m; m >>= 1) {
            s += __shfl_xor_sync(0xffffffffu, s, m);
            q += __shfl_xor_sync(0xffffffffu, q, m);
        }
        float mu  = s * (1.0f / 256.0f);
        float var = q * (1.0f / 256.0f) - mu * mu;
        float inv = rsqrtf(var + 1e-5f);
        int h0 = lane * 4, h1 = 128 + lane * 4;
        sm[r][h0+0] = (v0.x - mu) * inv * sc[h0+0] + bi[h0+0];
        sm[r][h0+1] = (v0.y - mu) * inv * sc[h0+1] + bi[h0+1];
        sm[r][h0+2] = (v0.z - mu) * inv * sc[h0+2] + bi[h0+2];
        sm[r][h0+3] = (v0.w - mu) * inv * sc[h0+3] + bi[h0+3];
        sm[r][h1+0] = (v1.x - mu) * inv * sc[h1+0] + bi[h1+0];
        sm[r][h1+1] = (v1.y - mu) * inv * sc[h1+1] + bi[h1+1];
        sm[r][h1+2] = (v1.z - mu) * inv * sc[h1+2] + bi[h1+2];
        sm[r][h1+3] = (v1.w - mu) * inv * sc[h1+3] + bi[h1+3];
    }
    __syncthreads();
    int b  = m0 >> 11;
    int l0 = m0 & 2047;
    for (int h = warp; h < HH; h += 8)
        g_zt[((size_t)(b * HH + h)) * LL + l0 + lane] = sm[lane][h];
}

__global__ void ssm_prep(const float* __restrict__ lre,
                         const float* __restrict__ lim,
                         const float* __restrict__ cre,
                         const float* __restrict__ cim,
                         const float* __restrict__ lstep) {
    int idx = blockIdx.x * blockDim.x + threadIdx.x;
    int h = idx >> 6, n = idx & 63;
    float Lre = lre[idx], Lim = lim[idx];
    float Cre = cre[idx], Cim = cim[idx];
    float dt  = expf(lstep[h]);
    float mag = expf(Lre * dt);
    float th  = Lim * dt;
    float dar = mag * cosf(th);
    float dai = mag * sinf(th);
    float den = Lre * Lre + Lim * Lim;
    float nr = dar - 1.0f, ni = dai;
    float dbr = (nr * Lre + ni * Lim) / den;
    float dbi = (ni * Lre - nr * Lim) / den;
    g_ar[idx]  = dar; g_ai[idx] = dai;
    g_w2r[idx] = 2.0f * (Cre * dbr - Cim * dbi);
    g_w2i[idx] = 2.0f * (Cre * dbi + Cim * dbr);
    float prr = 1.0f, pii = 0.0f;
    for (int t = 0; t < TB; ++t) {
        g_pr[(h * TB + t) * NN + n] = prr;
        g_pi[(h * TB + t) * NN + n] = pii;
        float tr = prr * dar - pii * dai;
        pii = prr * dai + pii * dar;
        prr = tr;
    }
    g_aTr[idx] = prr; g_aTi[idx] = pii;
}

__global__ void kv_build(const float* __restrict__ dcoef) {
    int idx = blockIdx.x * blockDim.x + threadIdx.x;
    int h = idx >> 6, d = idx & 63;
    const float* pr = &g_pr[(h * TB + d) * NN];
    const float* pi = &g_pi[(h * TB + d) * NN];
    const float* wr = &g_w2r[h * NN];
    const float* wi = &g_w2i[h * NN];
    float s = 0.0f;
    for (int n = 0; n < NN; ++n)
        s += wr[n] * pr[n] - wi[n] * pi[n];
    if (d == 0) s += dcoef[h];
    g_kv[idx] = s;
}

__global__ void pack_bl() {
    int idx = blockIdx.x * blockDim.x + threadIdx.x;
    int n  = idx % 192;
    int s2 = (idx / 192) & 31;
    int h  = idx / (192 * 32);
    int s0 = 2 * s2, s1 = s0 + 1;
    float x0, x1;
    if (n < 64) {
        x0 = (n >= s0) ? g_kv[h * 64 + n - s0] : 0.0f;
        x1 = (n >= s1) ? g_kv[h * 64 + n - s1] : 0.0f;
    } else if (n < 128) {
        int nn = n - 64;
        x0 = g_pr[(h * TB + 63 - s0) * NN + nn];
        x1 = g_pr[(h * TB + 63 - s1) * NN + nn];
    } else {
        int nn = n - 128;
        x0 = g_pi[(h * TB + 63 - s0) * NN + nn];
        x1 = g_pi[(h * TB + 63 - s1) * NN + nn];
    }
    float h0, l0, h1, l1;
    bsplit(x0, h0, l0); bsplit(x1, h1, l1);
    g_bl_hi[idx] = pkbf(h0, h1);
    g_bl_lo[idx] = pkbf(l0, l1);
}

__global__ void pack_bc() {
    int idx = blockIdx.x * blockDim.x + threadIdx.x;
    int t  = idx & 63;
    int k2 = (idx >> 6) & 63;
    int h  = idx >> 12;
    float x0, x1;
    if (k2 < 32) {
        x0 = g_pr[(h * TB + t) * NN + 2 * k2];
        x1 = g_pr[(h * TB + t) * NN + 2 * k2 + 1];
    } else {
        int kk = k2 - 32;
        x0 = -g_pi[(h * TB + t) * NN + 2 * kk];
        x1 = -g_pi[(h * TB + t) * NN + 2 * kk + 1];
    }
    float h0, l0, h1, l1;
    bsplit(x0, h0, l0); bsplit(x1, h1, l1);
    g_bc_hi[idx] = pkbf(h0, h1);
    g_bc_lo[idx] = pkbf(l0, l1);
}

#define SM_ER  (64 * 68)
#define SM_EI  (2 * 64 * 68)
#define SM_ST  (3 * 64 * 68)
#define ST_AH  0
#define ST_AL  (8 * 72)
#define ST_BH  (2 * 8 * 72)
#define ST_BL  (2 * 8 * 72 + 8 * 200)
#define SSM_SMEM ((3 * 64 * 68 + 2 * 8 * 72 + 2 * 8 * 200) * 4)

__global__ void __launch_bounds__(256) ssm_conv() {
    extern __shared__ float smf[];
    float* Ys = smf;
    float* Er = smf + SM_ER;
    float* Ei = smf + SM_EI;
    uint32_t* stg = reinterpret_cast<uint32_t*>(smf + SM_ST);
    uint32_t* Ah = stg + ST_AH;
    uint32_t* Al = stg + ST_AL;
    uint32_t* Bh = stg + ST_BH;
    uint32_t* Bl = stg + ST_BL;

    int tid  = threadIdx.x;
    int wid  = tid >> 5;
    int lane = tid & 31;
    int g    = lane >> 2;
    int t4   = lane & 3;
    int bx   = blockIdx.x;
    int h    = blockIdx.y;
    int b0   = bx * 2;

    const size_t zb0 = ((size_t)(b0 * HH + h)) * LL;
    const size_t zb1 = ((size_t)((b0 + 1) * HH + h)) * LL;

    // Phase 1: [Y | Er | Ei] = Z @ B  (64 x 192, K=64)
    int wm = wid & 1;
    int wn = wid >> 1;
    float acc[2][6][4];
    #pragma unroll
    for (int mi = 0; mi < 2; ++mi)
        #pragma unroll
        for (int nj = 0; nj < 6; ++nj)
            #pragma unroll
            for (int r = 0; r < 4; ++r) acc[mi][nj][r] = 0.0f;

    for (int c = 0; c < 4; ++c) {
        __syncthreads();
        {
            int m = tid & 63, q = tid >> 6;
            size_t zb = (m < 32) ? zb0 : zb1;
            int blk = m & 31;
            const float* src = g_zt + zb + blk * TB + c * 16 + q * 4;
            float4 v = *reinterpret_cast<const float4*>(src);
            float h0,l0,h1,l1,h2,l2,h3,l3;
            bsplit(v.x,h0,l0); bsplit(v.y,h1,l1);
            bsplit(v.z,h2,l2); bsplit(v.w,h3,l3);
            Ah[(q*2+0)*72 + m] = pkbf(h0,h1);  Al[(q*2+0)*72 + m] = pkbf(l0,l1);
            Ah[(q*2+1)*72 + m] = pkbf(h2,h3);  Al[(q*2+1)*72 + m] = pkbf(l2,l3);
        }
        {
            int k2l = tid >> 5, nb = tid & 31;
            size_t bb = ((size_t)h * 32 + c * 8 + k2l) * 192;
            #pragma unroll
            for (int j = 0; j < 6; ++j) {
                int n = nb + 32 * j;
                Bh[k2l * 200 + n] = g_bl_hi[bb + n];
                Bl[k2l * 200 + n] = g_bl_lo[bb + n];
            }
        }
        __syncthreads();
        #pragma unroll
        for (int mi = 0; mi < 2; ++mi) {
            int mr = wm * 32 + mi * 16 + g;
            uint32_t ah0 = Ah[t4*72 + mr],     ah1 = Ah[t4*72 + mr + 8];
            uint32_t ah2 = Ah[(t4+4)*72 + mr], ah3 = Ah[(t4+4)*72 + mr + 8];
            uint32_t al0 = Al[t4*72 + mr],     al1 = Al[t4*72 + mr + 8];
            uint32_t al2 = Al[(t4+4)*72 + mr], al3 = Al[(t4+4)*72 + mr + 8];
            #pragma unroll
            for (int nj = 0; nj < 6; ++nj) {
                int nc = wn * 48 + nj * 8 + g;
                uint32_t bh0 = Bh[t4*200 + nc], bh1 = Bh[(t4+4)*200 + nc];
                uint32_t bl0 = Bl[t4*200 + nc], bl1 = Bl[(t4+4)*200 + nc];
                mma_bf16(acc[mi][nj], ah0, ah1, ah2, ah3, bh0, bh1);
                mma_bf16(acc[mi][nj], ah0, ah1, ah2, ah3, bl0, bl1);
                mma_bf16(acc[mi][nj], al0, al1, al2, al3, bh0, bh1);
            }
        }
    }
    __syncthreads();
    #pragma unroll
    for (int mi = 0; mi < 2; ++mi) {
        #pragma unroll
        for (int nj = 0; nj < 6; ++nj) {
            int gn = wn * 48 + nj * 8;
            int colp = gn + t4 * 2;
            float* dst; int cc;
            if (gn < 64)       { dst = Ys; cc = colp; }
            else if (gn < 128) { dst = Er; cc = colp - 64; }
            else               { dst = Ei; cc = colp - 128; }
            int r = wm * 32 + mi * 16 + g;
            dst[r * 68 + cc]       = acc[mi][nj][0];
            dst[r * 68 + cc + 1]   = acc[mi][nj][1];
            dst[(r+8) * 68 + cc]   = acc[mi][nj][2];
            dst[(r+8) * 68 + cc+1] = acc[mi][nj][3];
        }
    }
    __syncthreads();

    // Phase 2: block scan, Er/Ei -> U (in place)
    if (tid < 128) {
        int bl = tid >> 6;
        int n  = tid & 63;
        int pidx = h * NN + n;
        float dar = g_ar[pidx],  dai = g_ai[pidx];
        float aTr = g_aTr[pidx], aTi = g_aTi[pidx];
        float w2r = g_w2r[pidx], w2i = g_w2i[pidx];
        float wdr = w2r * dar - w2i * dai;
        float wdi = w2r * dai + w2i * dar;
        float Sr = 0.f, Si = 0.f, epr = 0.f, epi = 0.f;
        for (int blk = 0; blk < NBLK; ++blk) {
            int row = bl * 32 + blk;
            float er = Er[row * 68 + n];
            float ei = Ei[row * 68 + n];
            float ur = 0.f, ui = 0.f;
            if (blk > 0) {
                float nsr = aTr * Sr - aTi * Si + epr;
                float nsi = aTr * Si + aTi * Sr + epi;
                Sr = nsr; Si = nsi;
                ur = wdr * Sr - wdi * Si;
                ui = wdr * Si + wdi * Sr;
            }
            Er[row * 68 + n] = ur;
            Ei[row * 68 + n] = ui;
            epr = er; epi = ei;
        }
    }

    // Phase 3: C = [Ur|Ui] @ Bc (64 x 64, K=128); y = gelu(Y + C)
    int wm2 = wid & 1;
    int wn2 = wid >> 1;
    float acc2[2][2][4];
    #pragma unroll
    for (int mi = 0; mi < 2; ++mi)
        #pragma unroll
        for (int nj = 0; nj < 2; ++nj)
            #pragma unroll
            for (int r = 0; r < 4; ++r) acc2[mi][nj][r] = 0.0f;

    for (int c = 0; c < 8; ++c) {
        __syncthreads();
        {
            int m = tid & 63, q = tid >> 6;
            int np = c * 16 + q * 4;
            const float* S = (np < 64) ? Er : Ei;
            int off = np & 63;
            float x0 = S[m*68 + off+0], x1 = S[m*68 + off+1];
            float x2 = S[m*68 + off+2], x3 = S[m*68 + off+3];
            float h0,l0,h1,l1,h2,l2,h3,l3;
            bsplit(x0,h0,l0); bsplit(x1,h1,l1);
            bsplit(x2,h2,l2); bsplit(x3,h3,l3);
            Ah[(q*2+0)*72 + m] = pkbf(h0,h1);  Al[(q*2+0)*72 + m] = pkbf(l0,l1);
            Ah[(q*2+1)*72 + m] = pkbf(h2,h3);  Al[(q*2+1)*72 + m] = pkbf(l2,l3);
        }
        {
            int k2l = tid >> 5, tb = tid & 31;
            size_t bb = ((size_t)h * 64 + c * 8 + k2l) * 64;
            #pragma unroll
            for (int j = 0; j < 2; ++j) {
                int tt = tb + 32 * j;
                Bh[k2l * 72 + tt] = g_bc_hi[bb + tt];
                Bl[k2l * 72 + tt] = g_bc_lo[bb + tt];
            }
        }
        __syncthreads();
        #pragma unroll
        for (int mi = 0; mi < 2; ++mi) {
            int mr = wm2 * 32 + mi * 16 + g;
            uint32_t ah0 = Ah[t4*72 + mr],     ah1 = Ah[t4*72 + mr + 8];
            uint32_t ah2 = Ah[(t4+4)*72 + mr], ah3 = Ah[(t4+4)*72 + mr + 8];
            uint32_t al0 = Al[t4*72 + mr],     al1 = Al[t4*72 + mr + 8];
            uint32_t al2 = Al[(t4+4)*72 + mr], al3 = Al[(t4+4)*72 + mr + 8];
            #pragma unroll
            for (int nj = 0; nj < 2; ++nj) {
                int nc = wn2 * 16 + nj * 8 + g;
                uint32_t bh0 = Bh[t4*72 + nc], bh1 = Bh[(t4+4)*72 + nc];
                uint32_t bl0 = Bl[t4*72 + nc], bl1 = Bl[(t4+4)*72 + nc];
                mma_bf16(acc2[mi][nj], ah0, ah1, ah2, ah3, bh0, bh1);
                mma_bf16(acc2[mi][nj], ah0, ah1, ah2, ah3, bl0, bl1);
                mma_bf16(acc2[mi][nj], al0, al1, al2, al3, bh0, bh1);
            }
        }
    }
    __syncthreads();
    #pragma unroll
    for (int mi = 0; mi < 2; ++mi) {
        #pragma unroll
        for (int nj = 0; nj < 2; ++nj) {
            int colp = wn2 * 16 + nj * 8 + t4 * 2;
            #pragma unroll
            for (int rr = 0; rr < 2; ++rr) {
                int r = wm2 * 32 + mi * 16 + g + rr * 8;
                float y0 = Ys[r * 68 + colp]     + acc2[mi][nj][rr*2+0];
                float y1 = Ys[r * 68 + colp + 1] + acc2[mi][nj][rr*2+1];
                y0 = gelu1(y0); y1 = gelu1(y1);
                int b  = b0 + (r >> 5);
                int blk = r & 31;
                float* dst = &g_yt[((size_t)(b * HH + h)) * LL + blk * TB + colp];
                *reinterpret_cast<float2*>(dst) = make_float2(y0, y1);
            }
        }
    }
}

#define ASTR 136
#define BSTR 72
__global__ void __launch_bounds__(256) glu_gemm_mma(
        const float* __restrict__ W1, const float* __restrict__ W2,
        const float* __restrict__ b1, const float* __restrict__ b2) {
    __shared__ uint32_t As [32 * ASTR];
    __shared__ uint32_t Bs1[32 * BSTR];
    __shared__ uint32_t Bs2[32 * BSTR];
    int tid  = threadIdx.x;
    int wid  = tid >> 5;
    int lane = tid & 31;
    int g    = lane >> 2;
    int t    = lane & 3;
    int wm   = wid & 3;
    int wn   = wid >> 2;
    int m0  = blockIdx.x * 128;
    int n0  = blockIdx.y * 64;
    int bch = m0 >> 11;
    int ml0 = m0 & 2047;

    float acc1[2][4][4];
    float acc2[2][4][4];
    #pragma unroll
    for (int mi = 0; mi < 2; ++mi)
        #pragma unroll
        for (int nj = 0; nj < 4; ++nj)
            #pragma unroll
            for (int r = 0; r < 4; ++r) { acc1[mi][nj][r] = 0.f; acc2[mi][nj][r] = 0.f; }

    for (int kc = 0; kc < HH; kc += 32) {
        __syncthreads();
        #pragma unroll
        for (int it = 0; it < 4; ++it) {
            int item = it * 256 + tid;
            int krow = item >> 5;
            int c4   = (item & 31) * 4;
            const float* src = &g_yt[(size_t)(bch * HH + kc + krow) * LL + ml0 + c4];
            float4 v = *reinterpret_cast<const float4*>(src);
            uint32_t* dst = &As[krow * ASTR + c4];
            asm volatile("st.shared.v4.b32 [%0], {%1,%2,%3,%4};"
                :: "l"(dst), "r"(f2tf32(v.x)), "r"(f2tf32(v.y)),
                   "r"(f2tf32(v.z)), "r"(f2tf32(v.w)) : "memory");
        }
        #pragma unroll
        for (int it = 0; it < 2; ++it) {
            int item = it * 256 + tid;
            int gg = item & 63;
            int kq = item >> 6;
            size_t off = (size_t)(n0 + gg) * HH + kc + kq * 4;
            float4 w1 = *reinterpret_cast<const float4*>(&W1[off]);
            float4 w2 = *reinterpret_cast<const float4*>(&W2[off]);
            int kb = kq * 4;
            Bs1[(kb+0) * BSTR + gg] = f2tf32(w1.x);
            Bs1[(kb+1) * BSTR + gg] = f2tf32(w1.y);
            Bs1[(kb+2) * BSTR + gg] = f2tf32(w1.z);
            Bs1[(kb+3) * BSTR + gg] = f2tf32(w1.w);
            Bs2[(kb+0) * BSTR + gg] = f2tf32(w2.x);
            Bs2[(kb+1) * BSTR + gg] = f2tf32(w2.y);
            Bs2[(kb+2) * BSTR + gg] = f2tf32(w2.z);
            Bs2[(kb+3) * BSTR + gg] = f2tf32(w2.w);
        }
        __syncthreads();
        #pragma unroll
        for (int ks = 0; ks < 4; ++ks) {
            int kb = ks * 8;
            uint32_t af[2][4];
            #pragma unroll
            for (int mi = 0; mi < 2; ++mi) {
                int mrow = wm * 32 + mi * 16;
                af[mi][0] = As[(kb + t)     * ASTR + mrow + g];
                af[mi][1] = As[(kb + t)     * ASTR + mrow + g + 8];
                af[mi][2] = As[(kb + t + 4) * ASTR + mrow + g];
                af[mi][3] = As[(kb + t + 4) * ASTR + mrow + g + 8];
            }
            #pragma unroll
            for (int nj = 0; nj < 4; ++nj) {
                int ncol = wn * 32 + nj * 8 + g;
                uint32_t bA0 = Bs1[(kb + t)     * BSTR + ncol];
                uint32_t bA1 = Bs1[(kb + t + 4) * BSTR + ncol];
                uint32_t bB0 = Bs2[(kb + t)     * BSTR + ncol];
                uint32_t bB1 = Bs2[(kb + t + 4) * BSTR + ncol];
                #pragma unroll
                for (int mi = 0; mi < 2; ++mi) {
                    mma_tf32(acc1[mi][nj], af[mi][0], af[mi][1], af[mi][2], af[mi][3], bA0, bA1);
                    mma_tf32(acc2[mi][nj], af[mi][0], af[mi][1], af[mi][2], af[mi][3], bB0, bB1);
                }
            }
        }
    }
    #pragma unroll
    for (int nj = 0; nj < 4; ++nj) {
        int ncol = n0 + wn * 32 + nj * 8 + t * 2;
        float bb1a = b1[ncol], bb1b = b1[ncol + 1];
        float bb2a = b2[ncol], bb2b = b2[ncol + 1];
        #pragma unroll
        for (int mi = 0; mi < 2; ++mi) {
            #pragma unroll
            for (int rr = 0; rr < 2; ++rr) {
                int mrow = m0 + wm * 32 + mi * 16 + g + rr * 8;
                float* hp = &g_h[(size_t)mrow * HH + ncol];
                float2 hv = *reinterpret_cast<float2*>(hp);
                float d1a = acc1[mi][nj][rr * 2 + 0] + bb1a;
                float d1b = acc1[mi][nj][rr * 2 + 1] + bb1b;
                float d2a = acc2[mi][nj][rr * 2 + 0] + bb2a;
                float d2b = acc2[mi][nj][rr * 2 + 1] + bb2b;
                hv.x += d1a * (1.0f / (1.0f + expf(-d2a)));
                hv.y += d1b * (1.0f / (1.0f + expf(-d2b)));
                *reinterpret_cast<float2*>(hp) = hv;
            }
        }
    }
}

__global__ void dec_kernel(const float* __restrict__ dw,
                           const float* __restrict__ db,
                           float* __restrict__ out) {
    int warp = (blockIdx.x * blockDim.x + threadIdx.x) >> 5;
    int lane = threadIdx.x & 31;
    const float* row = g_h + (size_t)warp * HH;
    float hr[8];
    #pragma unroll
    for (int k = 0; k < 8; ++k) hr[k] = row[lane + 32 * k];
    for (int o = 0; o < OUTD; ++o) {
        const float* wrow = dw + o * HH + lane;
        float acc = 0.0f;
        #pragma unroll
        for (int k = 0; k < 8; ++k) acc = fmaf(hr[k], wrow[32 * k], acc);
        #pragma unroll
        for (int m = 16; m; m >>= 1) acc += __shfl_xor_sync(0xffffffffu, acc, m);
        if (lane == 0) out[(size_t)warp * OUTD + o] = acc + db[o];
    }
}

extern "C" void kernel_launch(void* const* d_in, const int* in_sizes, int n_in,
                              void* d_out, int out_size) {
    const float* x     = (const float*)d_in[0];
    const float* enc_w = (const float*)d_in[1];
    const float* enc_b = (const float*)d_in[2];
    const float* lre   = (const float*)d_in[3];
    const float* lim   = (const float*)d_in[4];
    const float* cre   = (const float*)d_in[5];
    const float* cim   = (const float*)d_in[6];
    const float* dd    = (const float*)d_in[7];
    const float* lstep = (const float*)d_in[8];
    const float* lns   = (const float*)d_in[9];
    const float* lnb   = (const float*)d_in[10];
    const float* ow    = (const float*)d_in[11];
    const float* ob    = (const float*)d_in[12];
    const float* o2w   = (const float*)d_in[13];
    const float* o2b   = (const float*)d_in[14];
    const float* dw    = (const float*)d_in[15];
    const float* db    = (const float*)d_in[16];
    float* out = (float*)d_out;

    cudaFuncSetAttribute(ssm_conv,
                         cudaFuncAttributeMaxDynamicSharedMemorySize, SSM_SMEM);

    enc_kernel<<<(BB * LL) / 16, 256>>>(x, enc_w, enc_b);

    for (int li = 0; li < NLAY; ++li) {
        ln_kernel<<<(BB * LL) / 32, 256>>>(lns + li * HH, lnb + li * HH);
        ssm_prep<<<(HH * NN) / 256, 256>>>(
            lre + li * HH * NN, lim + li * HH * NN,
            cre + li * HH * NN, cim + li * HH * NN, lstep + li * HH);
        kv_build<<<(HH * TB) / 256, 256>>>(dd + li * HH);
        pack_bl<<<(HH * 32 * 192) / 256, 256>>>();
        pack_bc<<<(HH * 64 * 64) / 256, 256>>>();
        ssm_conv<<<dim3(8, HH), 256, SSM_SMEM>>>();
        glu_gemm_mma<<<dim3((BB * LL) / 128, HH / 64), 256>>>(
            ow + li * HH * HH, o2w + li * HH * HH,
            ob + li * HH, o2b + li * HH);
    }

    dec_kernel<<<(BB * LL) / 8, 256>>>(dw, db, out);
}

// round 12
// speedup vs baseline: 2.2478x; 1.0381x over previous
#include <cuda_runtime.h>
#include <cuda_bf16.h>
#include <math.h>
#include <stdint.h>

#define BB   16
#define LL   2048
#define HH   256
#define NN   64
#define NLAY 4
#define IND  40
#define OUTD 33
#define TB   64
#define NBLK 32
#define LH   (NLAY * HH)

typedef unsigned long long ull;

__device__ float g_h [BB * LL * HH];
__device__ float g_zt[BB * HH * LL];
__device__ float g_yt[BB * HH * LL];
__device__ float g_ar [LH * NN], g_ai [LH * NN];
__device__ float g_w2r[LH * NN], g_w2i[LH * NN];
__device__ float g_aTr[LH * NN], g_aTi[LH * NN];
__device__ float g_pr [LH * TB * NN], g_pi [LH * TB * NN];
__device__ float g_kv [LH * TB];
__device__ uint32_t g_bl_hi[LH * 32 * 192], g_bl_lo[LH * 32 * 192];
__device__ uint32_t g_bc_hi[LH * 64 * 64],  g_bc_lo[LH * 64 * 64];

__device__ __forceinline__ float gelu1(float x) {
    const float c0 = 0.7978845608028654f, c1 = 0.044715f;
    float t = tanhf(c0 * (x + c1 * x * x * x));
    return 0.5f * x * (1.0f + t);
}
__device__ __forceinline__ uint32_t f2tf32(float x) {
    uint32_t r; asm("cvt.rna.tf32.f32 %0, %1;" : "=r"(r) : "f"(x)); return r;
}
__device__ __forceinline__ uint32_t pkbf(float a, float b) {
    __nv_bfloat162 v = __floats2bfloat162_rn(a, b);
    return *reinterpret_cast<uint32_t*>(&v);
}
__device__ __forceinline__ void bsplit(float x, float& hi, float& lo) {
    float hf = __bfloat162float(__float2bfloat16(x));
    hi = hf; lo = x - hf;
}
__device__ __forceinline__ void mma_tf32(float c[4], uint32_t a0, uint32_t a1,
                                         uint32_t a2, uint32_t a3,
                                         uint32_t b0, uint32_t b1) {
    asm volatile("mma.sync.aligned.m16n8k8.row.col.f32.tf32.tf32.f32 "
        "{%0,%1,%2,%3}, {%4,%5,%6,%7}, {%8,%9}, {%0,%1,%2,%3};"
        : "+f"(c[0]), "+f"(c[1]), "+f"(c[2]), "+f"(c[3])
        : "r"(a0), "r"(a1), "r"(a2), "r"(a3), "r"(b0), "r"(b1));
}
__device__ __forceinline__ void mma_bf16(float c[4], uint32_t a0, uint32_t a1,
                                         uint32_t a2, uint32_t a3,
                                         uint32_t b0, uint32_t b1) {
    asm volatile("mma.sync.aligned.m16n8k16.row.col.f32.bf16.bf16.f32 "
        "{%0,%1,%2,%3}, {%4,%5,%6,%7}, {%8,%9}, {%0,%1,%2,%3};"
        : "+f"(c[0]), "+f"(c[1]), "+f"(c[2]), "+f"(c[3])
        : "r"(a0), "r"(a1), "r"(a2), "r"(a3), "r"(b0), "r"(b1));
}

__global__ void enc_kernel(const float* __restrict__ x,
                           const float* __restrict__ ew,
                           const float* __restrict__ eb) {
    __shared__ float sw[IND * HH];
    __shared__ float sx[16 * IND];
    int tid = threadIdx.x;
    for (int idx = tid; idx < HH * IND; idx += 256) {
        int h = idx / IND, i = idx % IND;
        sw[i * HH + h] = ew[idx];
    }
    int m0 = blockIdx.x * 16;
    for (int idx = tid; idx < 16 * IND; idx += 256)
        sx[idx] = x[(size_t)m0 * IND + idx];
    __syncthreads();
    float bias = eb[tid];
    for (int r = 0; r < 16; ++r) {
        float acc = bias;
        #pragma unroll
        for (int i = 0; i < IND; ++i)
            acc = fmaf(sx[r * IND + i], sw[i * HH + tid], acc);
        g_h[(size_t)(m0 + r) * HH + tid] = acc;
    }
}

__global__ void ln_kernel(const float* __restrict__ sc,
                          const float* __restrict__ bi) {
    __shared__ float sm[32][257];
    int tid  = threadIdx.x;
    int warp = tid >> 5;
    int lane = tid & 31;
    int m0 = blockIdx.x * 32;
    for (int r = warp; r < 32; r += 8) {
        const float* row = g_h + (size_t)(m0 + r) * HH;
        float4 v0 = *reinterpret_cast<const float4*>(row + lane * 4);
        float4 v1 = *reinterpret_cast<const float4*>(row + 128 + lane * 4);
        float s = v0.x + v0.y + v0.z + v0.w + v1.x + v1.y + v1.z + v1.w;
        float q = v0.x*v0.x + v0.y*v0.y + v0.z*v0.z + v0.w*v0.w
                + v1.x*v1.x + v1.y*v1.y + v1.z*v1.z + v1.w*v1.w;
        #pragma unroll
        for (int m = 16; m; m >>= 1) {
            s += __shfl_xor_sync(0xffffffffu, s, m);
            q += __shfl_xor_sync(0xffffffffu, q, m);
        }
        float mu  = s * (1.0f / 256.0f);
        float var = q * (1.0f / 256.0f) - mu * mu;
        float inv = rsqrtf(var + 1e-5f);
        int h0 = lane * 4, h1 = 128 + lane * 4;
        sm[r][h0+0] = (v0.x - mu) * inv * sc[h0+0] + bi[h0+0];
        sm[r][h0+1] = (v0.y - mu) * inv * sc[h0+1] + bi[h0+1];
        sm[r][h0+2] = (v0.z - mu) * inv * sc[h0+2] + bi[h0+2];
        sm[r][h0+3] = (v0.w - mu) * inv * sc[h0+3] + bi[h0+3];
        sm[r][h1+0] = (v1.x - mu) * inv * sc[h1+0] + bi[h1+0];
        sm[r][h1+1] = (v1.y - mu) * inv * sc[h1+1] + bi[h1+1];
        sm[r][h1+2] = (v1.z - mu) * inv * sc[h1+2] + bi[h1+2];
        sm[r][h1+3] = (v1.w - mu) * inv * sc[h1+3] + bi[h1+3];
    }
    __syncthreads();
    int b  = m0 >> 11;
    int l0 = m0 & 2047;
    for (int h = warp; h < HH; h += 8)
        g_zt[((size_t)(b * HH + h)) * LL + l0 + lane] = sm[lane][h];
}

// ------------------------------------------------------------------
// Batched (all-layer) parameter pipeline
// ------------------------------------------------------------------
__global__ void ssm_prep(const float* __restrict__ lre,
                         const float* __restrict__ lim,
                         const float* __restrict__ cre,
                         const float* __restrict__ cim,
                         const float* __restrict__ lstep) {
    int idx = blockIdx.x * blockDim.x + threadIdx.x;   // over LH*NN
    int lh = idx >> 6;
    float Lre = lre[idx], Lim = lim[idx];
    float Cre = cre[idx], Cim = cim[idx];
    float dt  = expf(lstep[lh]);
    float mag = expf(Lre * dt);
    float th  = Lim * dt;
    float dar = mag * cosf(th);
    float dai = mag * sinf(th);
    float den = Lre * Lre + Lim * Lim;
    float nr = dar - 1.0f, ni = dai;
    float dbr = (nr * Lre + ni * Lim) / den;
    float dbi = (ni * Lre - nr * Lim) / den;
    g_ar[idx]  = dar; g_ai[idx] = dai;
    g_w2r[idx] = 2.0f * (Cre * dbr - Cim * dbi);
    g_w2i[idx] = 2.0f * (Cre * dbi + Cim * dbr);
    float prr = 1.0f, pii = 0.0f;
    size_t pb = (size_t)lh * TB * NN + (idx & 63);
    for (int t = 0; t < TB; ++t) {
        g_pr[pb + (size_t)t * NN] = prr;
        g_pi[pb + (size_t)t * NN] = pii;
        float tr = prr * dar - pii * dai;
        pii = prr * dai + pii * dar;
        prr = tr;
    }
    g_aTr[idx] = prr; g_aTi[idx] = pii;
}

// warp per (lh, d): lanes split n (2 each), shfl reduce
__global__ void kv_build(const float* __restrict__ dcoef) {
    int gw   = (blockIdx.x * blockDim.x + threadIdx.x) >> 5;  // over LH*TB
    int lane = threadIdx.x & 31;
    int d  = gw & 63;
    int lh = gw >> 6;
    const float* pr = &g_pr[((size_t)lh * TB + d) * NN];
    const float* pi = &g_pi[((size_t)lh * TB + d) * NN];
    const float* wr = &g_w2r[lh * NN];
    const float* wi = &g_w2i[lh * NN];
    float s = wr[lane] * pr[lane] - wi[lane] * pi[lane];
    s += wr[lane + 32] * pr[lane + 32] - wi[lane + 32] * pi[lane + 32];
    #pragma unroll
    for (int m = 16; m; m >>= 1) s += __shfl_xor_sync(0xffffffffu, s, m);
    if (lane == 0) {
        if (d == 0) s += dcoef[lh];
        g_kv[lh * TB + d] = s;     // FIXED: single store per (lh, d)
    }
}

__global__ void pack_bl() {
    int idx = blockIdx.x * blockDim.x + threadIdx.x;   // over LH*32*192
    int n  = idx % 192;
    int s2 = (idx / 192) & 31;
    int lh = idx / (192 * 32);
    int s0 = 2 * s2, s1 = s0 + 1;
    float x0, x1;
    if (n < 64) {
        x0 = (n >= s0) ? g_kv[lh * 64 + n - s0] : 0.0f;
        x1 = (n >= s1) ? g_kv[lh * 64 + n - s1] : 0.0f;
    } else if (n < 128) {
        int nn = n - 64;
        x0 = g_pr[((size_t)lh * TB + 63 - s0) * NN + nn];
        x1 = g_pr[((size_t)lh * TB + 63 - s1) * NN + nn];
    } else {
        int nn = n - 128;
        x0 = g_pi[((size_t)lh * TB + 63 - s0) * NN + nn];
        x1 = g_pi[((size_t)lh * TB + 63 - s1) * NN + nn];
    }
    float h0, l0, h1, l1;
    bsplit(x0, h0, l0); bsplit(x1, h1, l1);
    g_bl_hi[idx] = pkbf(h0, h1);
    g_bl_lo[idx] = pkbf(l0, l1);
}

__global__ void pack_bc() {
    int idx = blockIdx.x * blockDim.x + threadIdx.x;   // over LH*64*64
    int t  = idx & 63;
    int k2 = (idx >> 6) & 63;
    int lh = idx >> 12;
    float x0, x1;
    if (k2 < 32) {
        x0 = g_pr[((size_t)lh * TB + t) * NN + 2 * k2];
        x1 = g_pr[((size_t)lh * TB + t) * NN + 2 * k2 + 1];
    } else {
        int kk = k2 - 32;
        x0 = -g_pi[((size_t)lh * TB + t) * NN + 2 * kk];
        x1 = -g_pi[((size_t)lh * TB + t) * NN + 2 * kk + 1];
    }
    float h0, l0, h1, l1;
    bsplit(x0, h0, l0); bsplit(x1, h1, l1);
    g_bc_hi[idx] = pkbf(h0, h1);
    g_bc_lo[idx] = pkbf(l0, l1);
}

#define SM_ER  (64 * 68)
#define SM_EI  (2 * 64 * 68)
#define SM_ST  (3 * 64 * 68)
#define ST_AH  0
#define ST_AL  (8 * 72)
#define ST_BH  (2 * 8 * 72)
#define ST_BL  (2 * 8 * 72 + 8 * 200)
#define SSM_SMEM ((3 * 64 * 68 + 2 * 8 * 72 + 2 * 8 * 200) * 4)

__global__ void __launch_bounds__(256) ssm_conv(int li) {
    extern __shared__ float smf[];
    float* Ys = smf;
    float* Er = smf + SM_ER;
    float* Ei = smf + SM_EI;
    uint32_t* stg = reinterpret_cast<uint32_t*>(smf + SM_ST);
    uint32_t* Ah = stg + ST_AH;
    uint32_t* Al = stg + ST_AL;
    uint32_t* Bh = stg + ST_BH;
    uint32_t* Bl = stg + ST_BL;

    int tid  = threadIdx.x;
    int wid  = tid >> 5;
    int lane = tid & 31;
    int g    = lane >> 2;
    int t4   = lane & 3;
    int bx   = blockIdx.x;
    int h    = blockIdx.y;
    int lh   = li * HH + h;
    int b0   = bx * 2;

    const size_t zb0 = ((size_t)(b0 * HH + h)) * LL;
    const size_t zb1 = ((size_t)((b0 + 1) * HH + h)) * LL;

    int wm = wid & 1;
    int wn = wid >> 1;
    float acc[2][6][4];
    #pragma unroll
    for (int mi = 0; mi < 2; ++mi)
        #pragma unroll
        for (int nj = 0; nj < 6; ++nj)
            #pragma unroll
            for (int r = 0; r < 4; ++r) acc[mi][nj][r] = 0.0f;

    for (int c = 0; c < 4; ++c) {
        __syncthreads();
        {
            int m = tid & 63, q = tid >> 6;
            size_t zb = (m < 32) ? zb0 : zb1;
            int blk = m & 31;
            const float* src = g_zt + zb + blk * TB + c * 16 + q * 4;
            float4 v = *reinterpret_cast<const float4*>(src);
            float h0,l0,h1,l1,h2,l2,h3,l3;
            bsplit(v.x,h0,l0); bsplit(v.y,h1,l1);
            bsplit(v.z,h2,l2); bsplit(v.w,h3,l3);
            Ah[(q*2+0)*72 + m] = pkbf(h0,h1);  Al[(q*2+0)*72 + m] = pkbf(l0,l1);
            Ah[(q*2+1)*72 + m] = pkbf(h2,h3);  Al[(q*2+1)*72 + m] = pkbf(l2,l3);
        }
        {
            int k2l = tid >> 5, nb = tid & 31;
            size_t bb = ((size_t)lh * 32 + c * 8 + k2l) * 192;
            #pragma unroll
            for (int j = 0; j < 6; ++j) {
                int n = nb + 32 * j;
                Bh[k2l * 200 + n] = g_bl_hi[bb + n];
                Bl[k2l * 200 + n] = g_bl_lo[bb + n];
            }
        }
        __syncthreads();
        #pragma unroll
        for (int mi = 0; mi < 2; ++mi) {
            int mr = wm * 32 + mi * 16 + g;
            uint32_t ah0 = Ah[t4*72 + mr],     ah1 = Ah[t4*72 + mr + 8];
            uint32_t ah2 = Ah[(t4+4)*72 + mr], ah3 = Ah[(t4+4)*72 + mr + 8];
            uint32_t al0 = Al[t4*72 + mr],     al1 = Al[t4*72 + mr + 8];
            uint32_t al2 = Al[(t4+4)*72 + mr], al3 = Al[(t4+4)*72 + mr + 8];
            #pragma unroll
            for (int nj = 0; nj < 6; ++nj) {
                int nc = wn * 48 + nj * 8 + g;
                uint32_t bh0 = Bh[t4*200 + nc], bh1 = Bh[(t4+4)*200 + nc];
                uint32_t bl0 = Bl[t4*200 + nc], bl1 = Bl[(t4+4)*200 + nc];
                mma_bf16(acc[mi][nj], ah0, ah1, ah2, ah3, bh0, bh1);
                mma_bf16(acc[mi][nj], ah0, ah1, ah2, ah3, bl0, bl1);
                mma_bf16(acc[mi][nj], al0, al1, al2, al3, bh0, bh1);
            }
        }
    }
    __syncthreads();
    #pragma unroll
    for (int mi = 0; mi < 2; ++mi) {
        #pragma unroll
        for (int nj = 0; nj < 6; ++nj) {
            int gn = wn * 48 + nj * 8;
            int colp = gn + t4 * 2;
            float* dst; int cc;
            if (gn < 64)       { dst = Ys; cc = colp; }
            else if (gn < 128) { dst = Er; cc = colp - 64; }
            else               { dst = Ei; cc = colp - 128; }
            int r = wm * 32 + mi * 16 + g;
            dst[r * 68 + cc]       = acc[mi][nj][0];
            dst[r * 68 + cc + 1]   = acc[mi][nj][1];
            dst[(r+8) * 68 + cc]   = acc[mi][nj][2];
            dst[(r+8) * 68 + cc+1] = acc[mi][nj][3];
        }
    }
    __syncthreads();

    if (tid < 128) {
        int bl = tid >> 6;
        int n  = tid & 63;
        int pidx = lh * NN + n;
        float dar = g_ar[pidx],  dai = g_ai[pidx];
        float aTr = g_aTr[pidx], aTi = g_aTi[pidx];
        float w2r = g_w2r[pidx], w2i = g_w2i[pidx];
        float wdr = w2r * dar - w2i * dai;
        float wdi = w2r * dai + w2i * dar;
        float Sr = 0.f, Si = 0.f, epr = 0.f, epi = 0.f;
        for (int blk = 0; blk < NBLK; ++blk) {
            int row = bl * 32 + blk;
            float er = Er[row * 68 + n];
            float ei = Ei[row * 68 + n];
            float ur = 0.f, ui = 0.f;
            if (blk > 0) {
                float nsr = aTr * Sr - aTi * Si + epr;
                float nsi = aTr * Si + aTi * Sr + epi;
                Sr = nsr; Si = nsi;
                ur = wdr * Sr - wdi * Si;
                ui = wdr * Si + wdi * Sr;
            }
            Er[row * 68 + n] = ur;
            Ei[row * 68 + n] = ui;
            epr = er; epi = ei;
        }
    }

    int wm2 = wid & 1;
    int wn2 = wid >> 1;
    float acc2[2][2][4];
    #pragma unroll
    for (int mi = 0; mi < 2; ++mi)
        #pragma unroll
        for (int nj = 0; nj < 2; ++nj)
            #pragma unroll
            for (int r = 0; r < 4; ++r) acc2[mi][nj][r] = 0.0f;

    for (int c = 0; c < 8; ++c) {
        __syncthreads();
        {
            int m = tid & 63, q = tid >> 6;
            int np = c * 16 + q * 4;
            const float* S = (np < 64) ? Er : Ei;
            int off = np & 63;
            float x0 = S[m*68 + off+0], x1 = S[m*68 + off+1];
            float x2 = S[m*68 + off+2], x3 = S[m*68 + off+3];
            float h0,l0,h1,l1,h2,l2,h3,l3;
            bsplit(x0,h0,l0); bsplit(x1,h1,l1);
            bsplit(x2,h2,l2); bsplit(x3,h3,l3);
            Ah[(q*2+0)*72 + m] = pkbf(h0,h1);  Al[(q*2+0)*72 + m] = pkbf(l0,l1);
            Ah[(q*2+1)*72 + m] = pkbf(h2,h3);  Al[(q*2+1)*72 + m] = pkbf(l2,l3);
        }
        {
            int k2l = tid >> 5, tb = tid & 31;
            size_t bb = ((size_t)lh * 64 + c * 8 + k2l) * 64;
            #pragma unroll
            for (int j = 0; j < 2; ++j) {
                int tt = tb + 32 * j;
                Bh[k2l * 72 + tt] = g_bc_hi[bb + tt];
                Bl[k2l * 72 + tt] = g_bc_lo[bb + tt];
            }
        }
        __syncthreads();
        #pragma unroll
        for (int mi = 0; mi < 2; ++mi) {
            int mr = wm2 * 32 + mi * 16 + g;
            uint32_t ah0 = Ah[t4*72 + mr],     ah1 = Ah[t4*72 + mr + 8];
            uint32_t ah2 = Ah[(t4+4)*72 + mr], ah3 = Ah[(t4+4)*72 + mr + 8];
            uint32_t al0 = Al[t4*72 + mr],     al1 = Al[t4*72 + mr + 8];
            uint32_t al2 = Al[(t4+4)*72 + mr], al3 = Al[(t4+4)*72 + mr + 8];
            #pragma unroll
            for (int nj = 0; nj < 2; ++nj) {
                int nc = wn2 * 16 + nj * 8 + g;
                uint32_t bh0 = Bh[t4*72 + nc], bh1 = Bh[(t4+4)*72 + nc];
                uint32_t bl0 = Bl[t4*72 + nc], bl1 = Bl[(t4+4)*72 + nc];
                mma_bf16(acc2[mi][nj], ah0, ah1, ah2, ah3, bh0, bh1);
                mma_bf16(acc2[mi][nj], ah0, ah1, ah2, ah3, bl0, bl1);
                mma_bf16(acc2[mi][nj], al0, al1, al2, al3, bh0, bh1);
            }
        }
    }
    __syncthreads();
    #pragma unroll
    for (int mi = 0; mi < 2; ++mi) {
        #pragma unroll
        for (int nj = 0; nj < 2; ++nj) {
            int colp = wn2 * 16 + nj * 8 + t4 * 2;
            #pragma unroll
            for (int rr = 0; rr < 2; ++rr) {
                int r = wm2 * 32 + mi * 16 + g + rr * 8;
                float y0 = Ys[r * 68 + colp]     + acc2[mi][nj][rr*2+0];
                float y1 = Ys[r * 68 + colp + 1] + acc2[mi][nj][rr*2+1];
                y0 = gelu1(y0); y1 = gelu1(y1);
                int b  = b0 + (r >> 5);
                int blk = r & 31;
                float* dst = &g_yt[((size_t)(b * HH + h)) * LL + blk * TB + colp];
                *reinterpret_cast<float2*>(dst) = make_float2(y0, y1);
            }
        }
    }
}

#define ASTR 136
#define BSTR 72
__global__ void __launch_bounds__(256) glu_gemm_mma(
        const float* __restrict__ W1, const float* __restrict__ W2,
        const float* __restrict__ b1, const float* __restrict__ b2) {
    __shared__ uint32_t As [32 * ASTR];
    __shared__ uint32_t Bs1[32 * BSTR];
    __shared__ uint32_t Bs2[32 * BSTR];
    int tid  = threadIdx.x;
    int wid  = tid >> 5;
    int lane = tid & 31;
    int g    = lane >> 2;
    int t    = lane & 3;
    int wm   = wid & 3;
    int wn   = wid >> 2;
    int m0  = blockIdx.x * 128;
    int n0  = blockIdx.y * 64;
    int bch = m0 >> 11;
    int ml0 = m0 & 2047;

    float acc1[2][4][4];
    float acc2[2][4][4];
    #pragma unroll
    for (int mi = 0; mi < 2; ++mi)
        #pragma unroll
        for (int nj = 0; nj < 4; ++nj)
            #pragma unroll
            for (int r = 0; r < 4; ++r) { acc1[mi][nj][r] = 0.f; acc2[mi][nj][r] = 0.f; }

    for (int kc = 0; kc < HH; kc += 32) {
        __syncthreads();
        #pragma unroll
        for (int it = 0; it < 4; ++it) {
            int item = it * 256 + tid;
            int krow = item >> 5;
            int c4   = (item & 31) * 4;
            const float* src = &g_yt[(size_t)(bch * HH + kc + krow) * LL + ml0 + c4];
            float4 v = *reinterpret_cast<const float4*>(src);
            uint32_t* dst = &As[krow * ASTR + c4];
            asm volatile("st.shared.v4.b32 [%0], {%1,%2,%3,%4};"
                :: "l"(dst), "r"(f2tf32(v.x)), "r"(f2tf32(v.y)),
                   "r"(f2tf32(v.z)), "r"(f2tf32(v.w)) : "memory");
        }
        #pragma unroll
        for (int it = 0; it < 2; ++it) {
            int item = it * 256 + tid;
            int gg = item & 63;
            int kq = item >> 6;
            size_t off = (size_t)(n0 + gg) * HH + kc + kq * 4;
            float4 w1 = *reinterpret_cast<const float4*>(&W1[off]);
            float4 w2 = *reinterpret_cast<const float4*>(&W2[off]);
            int kb = kq * 4;
            Bs1[(kb+0) * BSTR + gg] = f2tf32(w1.x);
            Bs1[(kb+1) * BSTR + gg] = f2tf32(w1.y);
            Bs1[(kb+2) * BSTR + gg] = f2tf32(w1.z);
            Bs1[(kb+3) * BSTR + gg] = f2tf32(w1.w);
            Bs2[(kb+0) * BSTR + gg] = f2tf32(w2.x);
            Bs2[(kb+1) * BSTR + gg] = f2tf32(w2.y);
            Bs2[(kb+2) * BSTR + gg] = f2tf32(w2.z);
            Bs2[(kb+3) * BSTR + gg] = f2tf32(w2.w);
        }
        __syncthreads();
        #pragma unroll
        for (int ks = 0; ks < 4; ++ks) {
            int kb = ks * 8;
            uint32_t af[2][4];
            #pragma unroll
            for (int mi = 0; mi < 2; ++mi) {
                int mrow = wm * 32 + mi * 16;
                af[mi][0] = As[(kb + t)     * ASTR + mrow + g];
                af[mi][1] = As[(kb + t)     * ASTR + mrow + g + 8];
                af[mi][2] = As[(kb + t + 4) * ASTR + mrow + g];
                af[mi][3] = As[(kb + t + 4) * ASTR + mrow + g + 8];
            }
            #pragma unroll
            for (int nj = 0; nj < 4; ++nj) {
                int ncol = wn * 32 + nj * 8 + g;
                uint32_t bA0 = Bs1[(kb + t)     * BSTR + ncol];
                uint32_t bA1 = Bs1[(kb + t + 4) * BSTR + ncol];
                uint32_t bB0 = Bs2[(kb + t)     * BSTR + ncol];
                uint32_t bB1 = Bs2[(kb + t + 4) * BSTR + ncol];
                #pragma unroll
                for (int mi = 0; mi < 2; ++mi) {
                    mma_tf32(acc1[mi][nj], af[mi][0], af[mi][1], af[mi][2], af[mi][3], bA0, bA1);
                    mma_tf32(acc2[mi][nj], af[mi][0], af[mi][1], af[mi][2], af[mi][3], bB0, bB1);
                }
            }
        }
    }
    #pragma unroll
    for (int nj = 0; nj < 4; ++nj) {
        int ncol = n0 + wn * 32 + nj * 8 + t * 2;
        float bb1a = b1[ncol], bb1b = b1[ncol + 1];
        float bb2a = b2[ncol], bb2b = b2[ncol + 1];
        #pragma unroll
        for (int mi = 0; mi < 2; ++mi) {
            #pragma unroll
            for (int rr = 0; rr < 2; ++rr) {
                int mrow = m0 + wm * 32 + mi * 16 + g + rr * 8;
                float* hp = &g_h[(size_t)mrow * HH + ncol];
                float2 hv = *reinterpret_cast<float2*>(hp);
                float d1a = acc1[mi][nj][rr * 2 + 0] + bb1a;
                float d1b = acc1[mi][nj][rr * 2 + 1] + bb1b;
                float d2a = acc2[mi][nj][rr * 2 + 0] + bb2a;
                float d2b = acc2[mi][nj][rr * 2 + 1] + bb2b;
                hv.x += d1a * (1.0f / (1.0f + expf(-d2a)));
                hv.y += d1b * (1.0f / (1.0f + expf(-d2b)));
                *reinterpret_cast<float2*>(hp) = hv;
            }
        }
    }
}

__global__ void dec_kernel(const float* __restrict__ dw,
                           const float* __restrict__ db,
                           float* __restrict__ out) {
    int warp = (blockIdx.x * blockDim.x + threadIdx.x) >> 5;
    int lane = threadIdx.x & 31;
    const float* row = g_h + (size_t)warp * HH;
    float hr[8];
    #pragma unroll
    for (int k = 0; k < 8; ++k) hr[k] = row[lane + 32 * k];
    for (int o = 0; o < OUTD; ++o) {
        const float* wrow = dw + o * HH + lane;
        float acc = 0.0f;
        #pragma unroll
        for (int k = 0; k < 8; ++k) acc = fmaf(hr[k], wrow[32 * k], acc);
        #pragma unroll
        for (int m = 16; m; m >>= 1) acc += __shfl_xor_sync(0xffffffffu, acc, m);
        if (lane == 0) out[(size_t)warp * OUTD + o] = acc + db[o];
    }
}

extern "C" void kernel_launch(void* const* d_in, const int* in_sizes, int n_in,
                              void* d_out, int out_size) {
    const float* x     = (const float*)d_in[0];
    const float* enc_w = (const float*)d_in[1];
    const float* enc_b = (const float*)d_in[2];
    const float* lre   = (const float*)d_in[3];
    const float* lim   = (const float*)d_in[4];
    const float* cre   = (const float*)d_in[5];
    const float* cim   = (const float*)d_in[6];
    const float* dd    = (const float*)d_in[7];
    const float* lstep = (const float*)d_in[8];
    const float* lns   = (const float*)d_in[9];
    const float* lnb   = (const float*)d_in[10];
    const float* ow    = (const float*)d_in[11];
    const float* ob    = (const float*)d_in[12];
    const float* o2w   = (const float*)d_in[13];
    const float* o2b   = (const float*)d_in[14];
    const float* dw    = (const float*)d_in[15];
    const float* db    = (const float*)d_in[16];
    float* out = (float*)d_out;

    cudaFuncSetAttribute(ssm_conv,
                         cudaFuncAttributeMaxDynamicSharedMemorySize, SSM_SMEM);

    // Parameter pipeline for ALL layers, batched, up front.
    ssm_prep<<<(LH * NN) / 256, 256>>>(lre, lim, cre, cim, lstep);
    kv_build<<<(LH * TB * 32) / 256, 256>>>(dd);
    pack_bl<<<(LH * 32 * 192) / 256, 256>>>();
    pack_bc<<<(LH * 64 * 64) / 256, 256>>>();

    enc_kernel<<<(BB * LL) / 16, 256>>>(x, enc_w, enc_b);

    for (int li = 0; li < NLAY; ++li) {
        ln_kernel<<<(BB * LL) / 32, 256>>>(lns + li * HH, lnb + li * HH);
        ssm_conv<<<dim3(8, HH), 256, SSM_SMEM>>>(li);
        glu_gemm_mma<<<dim3((BB * LL) / 128, HH / 64), 256>>>(
            ow + li * HH * HH, o2w + li * HH * HH,
            ob + li * HH, o2b + li * HH);
    }

    dec_kernel<<<(BB * LL) / 8, 256>>>(dw, db, out);
}

// round 13
// speedup vs baseline: 2.3168x; 1.0307x over previous
#include <cuda_runtime.h>
#include <cuda_bf16.h>
#include <math.h>
#include <stdint.h>

#define BB   16
#define LL   2048
#define HH   256
#define NN   64
#define NLAY 4
#define IND  40
#define OUTD 33
#define TB   64
#define NBLK 32
#define LH   (NLAY * HH)

typedef unsigned long long ull;

__device__ float g_h [BB * LL * HH];
__device__ float g_zt[BB * HH * LL];
__device__ float g_yt[BB * HH * LL];
__device__ float g_ar [LH * NN], g_ai [LH * NN];
__device__ float g_w2r[LH * NN], g_w2i[LH * NN];
__device__ float g_aTr[LH * NN], g_aTi[LH * NN];
__device__ float g_pr [LH * TB * NN], g_pi [LH * TB * NN];
__device__ float g_kv [LH * TB];
__device__ uint32_t g_bl[LH * 64 * 192];   // tf32 B for GEMM1 [lh][k=64][n=192]
__device__ uint32_t g_bc[LH * 128 * 64];   // tf32 B for GEMM2 [lh][k=128][t=64]

__device__ __forceinline__ float gelu1(float x) {
    const float c0 = 0.7978845608028654f, c1 = 0.044715f;
    float t = tanhf(c0 * (x + c1 * x * x * x));
    return 0.5f * x * (1.0f + t);
}
__device__ __forceinline__ uint32_t f2tf32(float x) {
    uint32_t r; asm("cvt.rna.tf32.f32 %0, %1;" : "=r"(r) : "f"(x)); return r;
}
__device__ __forceinline__ void mma_tf32(float c[4], uint32_t a0, uint32_t a1,
                                         uint32_t a2, uint32_t a3,
                                         uint32_t b0, uint32_t b1) {
    asm volatile("mma.sync.aligned.m16n8k8.row.col.f32.tf32.tf32.f32 "
        "{%0,%1,%2,%3}, {%4,%5,%6,%7}, {%8,%9}, {%0,%1,%2,%3};"
        : "+f"(c[0]), "+f"(c[1]), "+f"(c[2]), "+f"(c[3])
        : "r"(a0), "r"(a1), "r"(a2), "r"(a3), "r"(b0), "r"(b1));
}

__global__ void enc_kernel(const float* __restrict__ x,
                           const float* __restrict__ ew,
                           const float* __restrict__ eb) {
    __shared__ float sw[IND * HH];
    __shared__ float sx[16 * IND];
    int tid = threadIdx.x;
    for (int idx = tid; idx < HH * IND; idx += 256) {
        int h = idx / IND, i = idx % IND;
        sw[i * HH + h] = ew[idx];
    }
    int m0 = blockIdx.x * 16;
    for (int idx = tid; idx < 16 * IND; idx += 256)
        sx[idx] = x[(size_t)m0 * IND + idx];
    __syncthreads();
    float bias = eb[tid];
    for (int r = 0; r < 16; ++r) {
        float acc = bias;
        #pragma unroll
        for (int i = 0; i < IND; ++i)
            acc = fmaf(sx[r * IND + i], sw[i * HH + tid], acc);
        g_h[(size_t)(m0 + r) * HH + tid] = acc;
    }
}

__global__ void ln_kernel(const float* __restrict__ sc,
                          const float* __restrict__ bi) {
    __shared__ float sm[32][257];
    int tid  = threadIdx.x;
    int warp = tid >> 5;
    int lane = tid & 31;
    int m0 = blockIdx.x * 32;
    for (int r = warp; r < 32; r += 8) {
        const float* row = g_h + (size_t)(m0 + r) * HH;
        float4 v0 = *reinterpret_cast<const float4*>(row + lane * 4);
        float4 v1 = *reinterpret_cast<const float4*>(row + 128 + lane * 4);
        float s = v0.x + v0.y + v0.z + v0.w + v1.x + v1.y + v1.z + v1.w;
        float q = v0.x*v0.x + v0.y*v0.y + v0.z*v0.z + v0.w*v0.w
                + v1.x*v1.x + v1.y*v1.y + v1.z*v1.z + v1.w*v1.w;
        #pragma unroll
        for (int m = 16; m; m >>= 1) {
            s += __shfl_xor_sync(0xffffffffu, s, m);
            q += __shfl_xor_sync(0xffffffffu, q, m);
        }
        float mu  = s * (1.0f / 256.0f);
        float var = q * (1.0f / 256.0f) - mu * mu;
        float inv = rsqrtf(var + 1e-5f);
        int h0 = lane * 4, h1 = 128 + lane * 4;
        sm[r][h0+0] = (v0.x - mu) * inv * sc[h0+0] + bi[h0+0];
        sm[r][h0+1] = (v0.y - mu) * inv * sc[h0+1] + bi[h0+1];
        sm[r][h0+2] = (v0.z - mu) * inv * sc[h0+2] + bi[h0+2];
        sm[r][h0+3] = (v0.w - mu) * inv * sc[h0+3] + bi[h0+3];
        sm[r][h1+0] = (v1.x - mu) * inv * sc[h1+0] + bi[h1+0];
        sm[r][h1+1] = (v1.y - mu) * inv * sc[h1+1] + bi[h1+1];
        sm[r][h1+2] = (v1.z - mu) * inv * sc[h1+2] + bi[h1+2];
        sm[r][h1+3] = (v1.w - mu) * inv * sc[h1+3] + bi[h1+3];
    }
    __syncthreads();
    int b  = m0 >> 11;
    int l0 = m0 & 2047;
    for (int h = warp; h < HH; h += 8)
        g_zt[((size_t)(b * HH + h)) * LL + l0 + lane] = sm[lane][h];
}

// ------------------------------------------------------------------
// Batched (all-layer) parameter pipeline
// ------------------------------------------------------------------
__global__ void ssm_prep(const float* __restrict__ lre,
                         const float* __restrict__ lim,
                         const float* __restrict__ cre,
                         const float* __restrict__ cim,
                         const float* __restrict__ lstep) {
    int idx = blockIdx.x * blockDim.x + threadIdx.x;   // over LH*NN
    int lh = idx >> 6;
    float Lre = lre[idx], Lim = lim[idx];
    float Cre = cre[idx], Cim = cim[idx];
    float dt  = expf(lstep[lh]);
    float mag = expf(Lre * dt);
    float th  = Lim * dt;
    float dar = mag * cosf(th);
    float dai = mag * sinf(th);
    float den = Lre * Lre + Lim * Lim;
    float nr = dar - 1.0f, ni = dai;
    float dbr = (nr * Lre + ni * Lim) / den;
    float dbi = (ni * Lre - nr * Lim) / den;
    g_ar[idx]  = dar; g_ai[idx] = dai;
    g_w2r[idx] = 2.0f * (Cre * dbr - Cim * dbi);
    g_w2i[idx] = 2.0f * (Cre * dbi + Cim * dbr);
    float prr = 1.0f, pii = 0.0f;
    size_t pb = (size_t)lh * TB * NN + (idx & 63);
    for (int t = 0; t < TB; ++t) {
        g_pr[pb + (size_t)t * NN] = prr;
        g_pi[pb + (size_t)t * NN] = pii;
        float tr = prr * dar - pii * dai;
        pii = prr * dai + pii * dar;
        prr = tr;
    }
    g_aTr[idx] = prr; g_aTi[idx] = pii;
}

// warp per (lh, d): lanes split n (2 each), shfl reduce
__global__ void kv_build(const float* __restrict__ dcoef) {
    int gw   = (blockIdx.x * blockDim.x + threadIdx.x) >> 5;
    int lane = threadIdx.x & 31;
    int d  = gw & 63;
    int lh = gw >> 6;
    const float* pr = &g_pr[((size_t)lh * TB + d) * NN];
    const float* pi = &g_pi[((size_t)lh * TB + d) * NN];
    const float* wr = &g_w2r[lh * NN];
    const float* wi = &g_w2i[lh * NN];
    float s = wr[lane] * pr[lane] - wi[lane] * pi[lane];
    s += wr[lane + 32] * pr[lane + 32] - wi[lane + 32] * pi[lane + 32];
    #pragma unroll
    for (int m = 16; m; m >>= 1) s += __shfl_xor_sync(0xffffffffu, s, m);
    if (lane == 0) {
        if (d == 0) s += dcoef[lh];
        g_kv[lh * TB + d] = s;
    }
}

// tf32 pack of GEMM1 B: [lh][s=64][n=192]
__global__ void pack_bl() {
    int idx = blockIdx.x * blockDim.x + threadIdx.x;   // over LH*64*192
    int n  = idx % 192;
    int s  = (idx / 192) & 63;
    int lh = idx / (192 * 64);
    float x;
    if (n < 64) {
        x = (n >= s) ? g_kv[lh * 64 + n - s] : 0.0f;
    } else if (n < 128) {
        x = g_pr[((size_t)lh * TB + 63 - s) * NN + (n - 64)];
    } else {
        x = g_pi[((size_t)lh * TB + 63 - s) * NN + (n - 128)];
    }
    g_bl[idx] = f2tf32(x);
}

// tf32 pack of GEMM2 B: [lh][k=128][t=64]; k<64 -> Pr, k>=64 -> -Pi
__global__ void pack_bc() {
    int idx = blockIdx.x * blockDim.x + threadIdx.x;   // over LH*128*64
    int t  = idx & 63;
    int k  = (idx >> 6) & 127;
    int lh = idx >> 13;
    float x = (k < 64)
        ?  g_pr[((size_t)lh * TB + t) * NN + k]
        : -g_pi[((size_t)lh * TB + t) * NN + (k - 64)];
    g_bc[idx] = f2tf32(x);
}

// ------------------------------------------------------------------
// Fused SSM block-conv kernel, tf32 tensor cores.
// smem: Ys/Er/Ei [64][68] + As[16][72] + Bs[16][200]
// ------------------------------------------------------------------
#define SM_ER  (64 * 68)
#define SM_EI  (2 * 64 * 68)
#define SM_ST  (3 * 64 * 68)
#define ST_A   0
#define ST_B   (16 * 72)
#define SSM_SMEM ((3 * 64 * 68 + 16 * 72 + 16 * 200) * 4)

__global__ void __launch_bounds__(256) ssm_conv(int li) {
    extern __shared__ float smf[];
    float* Ys = smf;
    float* Er = smf + SM_ER;
    float* Ei = smf + SM_EI;
    uint32_t* stg = reinterpret_cast<uint32_t*>(smf + SM_ST);
    uint32_t* As = stg + ST_A;
    uint32_t* Bs = stg + ST_B;

    int tid  = threadIdx.x;
    int wid  = tid >> 5;
    int lane = tid & 31;
    int g    = lane >> 2;
    int t4   = lane & 3;
    int bx   = blockIdx.x;
    int h    = blockIdx.y;
    int lh   = li * HH + h;
    int b0   = bx * 2;

    const size_t zb0 = ((size_t)(b0 * HH + h)) * LL;
    const size_t zb1 = ((size_t)((b0 + 1) * HH + h)) * LL;

    // ---- Phase 1: [Y | Er | Ei] = Z @ Bl  (64m x 192n, K=64, tf32) ----
    int wm = wid & 1;          // m half
    int wn = wid >> 1;         // n quarter (48 cols)
    float acc[2][6][4];
    #pragma unroll
    for (int mi = 0; mi < 2; ++mi)
        #pragma unroll
        for (int nj = 0; nj < 6; ++nj)
            #pragma unroll
            for (int r = 0; r < 4; ++r) acc[mi][nj][r] = 0.0f;

    for (int c = 0; c < 4; ++c) {
        __syncthreads();
        {   // stage A: Z tile -> As[k][m], k = c*16..c*16+15
            int m = tid & 63, q = tid >> 6;
            size_t zb = (m < 32) ? zb0 : zb1;
            int blk = m & 31;
            const float* src = g_zt + zb + blk * TB + c * 16 + q * 4;
            float4 v = *reinterpret_cast<const float4*>(src);
            As[(q*4+0)*72 + m] = f2tf32(v.x);
            As[(q*4+1)*72 + m] = f2tf32(v.y);
            As[(q*4+2)*72 + m] = f2tf32(v.z);
            As[(q*4+3)*72 + m] = f2tf32(v.w);
        }
        {   // stage B: g_bl [16 k][192 n]
            int krow = tid >> 4, nb = tid & 15;
            size_t bb = ((size_t)lh * 64 + c * 16 + krow) * 192;
            #pragma unroll
            for (int j = 0; j < 12; ++j) {
                int n = nb + 16 * j;
                Bs[krow * 200 + n] = g_bl[bb + n];
            }
        }
        __syncthreads();
        #pragma unroll
        for (int ks = 0; ks < 2; ++ks) {
            int kb = ks * 8;
            #pragma unroll
            for (int mi = 0; mi < 2; ++mi) {
                int mr = wm * 32 + mi * 16 + g;
                uint32_t a0 = As[(kb + t4)     * 72 + mr];
                uint32_t a1 = As[(kb + t4)     * 72 + mr + 8];
                uint32_t a2 = As[(kb + t4 + 4) * 72 + mr];
                uint32_t a3 = As[(kb + t4 + 4) * 72 + mr + 8];
                #pragma unroll
                for (int nj = 0; nj < 6; ++nj) {
                    int nc = wn * 48 + nj * 8 + g;
                    uint32_t b0 = Bs[(kb + t4)     * 200 + nc];
                    uint32_t b1 = Bs[(kb + t4 + 4) * 200 + nc];
                    mma_tf32(acc[mi][nj], a0, a1, a2, a3, b0, b1);
                }
            }
        }
    }
    __syncthreads();
    #pragma unroll
    for (int mi = 0; mi < 2; ++mi) {
        #pragma unroll
        for (int nj = 0; nj < 6; ++nj) {
            int gn = wn * 48 + nj * 8;
            int colp = gn + t4 * 2;
            float* dst; int cc;
            if (gn < 64)       { dst = Ys; cc = colp; }
            else if (gn < 128) { dst = Er; cc = colp - 64; }
            else               { dst = Ei; cc = colp - 128; }
            int r = wm * 32 + mi * 16 + g;
            dst[r * 68 + cc]       = acc[mi][nj][0];
            dst[r * 68 + cc + 1]   = acc[mi][nj][1];
            dst[(r+8) * 68 + cc]   = acc[mi][nj][2];
            dst[(r+8) * 68 + cc+1] = acc[mi][nj][3];
        }
    }
    __syncthreads();

    // ---- Phase 2: block scan, Er/Ei -> U (in place) ----
    if (tid < 128) {
        int bl = tid >> 6;
        int n  = tid & 63;
        int pidx = lh * NN + n;
        float dar = g_ar[pidx],  dai = g_ai[pidx];
        float aTr = g_aTr[pidx], aTi = g_aTi[pidx];
        float w2r = g_w2r[pidx], w2i = g_w2i[pidx];
        float wdr = w2r * dar - w2i * dai;
        float wdi = w2r * dai + w2i * dar;
        float Sr = 0.f, Si = 0.f, epr = 0.f, epi = 0.f;
        for (int blk = 0; blk < NBLK; ++blk) {
            int row = bl * 32 + blk;
            float er = Er[row * 68 + n];
            float ei = Ei[row * 68 + n];
            float ur = 0.f, ui = 0.f;
            if (blk > 0) {
                float nsr = aTr * Sr - aTi * Si + epr;
                float nsi = aTr * Si + aTi * Sr + epi;
                Sr = nsr; Si = nsi;
                ur = wdr * Sr - wdi * Si;
                ui = wdr * Si + wdi * Sr;
            }
            Er[row * 68 + n] = ur;
            Ei[row * 68 + n] = ui;
            epr = er; epi = ei;
        }
    }

    // ---- Phase 3: C = [Ur|Ui] @ Bc (64m x 64t, K=128, tf32) ----
    int wm2 = wid & 1;
    int wn2 = wid >> 1;
    float acc2[2][2][4];
    #pragma unroll
    for (int mi = 0; mi < 2; ++mi)
        #pragma unroll
        for (int nj = 0; nj < 2; ++nj)
            #pragma unroll
            for (int r = 0; r < 4; ++r) acc2[mi][nj][r] = 0.0f;

    for (int c = 0; c < 8; ++c) {
        __syncthreads();
        {   // stage A from smem U
            int m = tid & 63, q = tid >> 6;
            int np = c * 16 + q * 4;
            const float* S = (np < 64) ? Er : Ei;
            int off = np & 63;
            As[(q*4+0)*72 + m] = f2tf32(S[m*68 + off+0]);
            As[(q*4+1)*72 + m] = f2tf32(S[m*68 + off+1]);
            As[(q*4+2)*72 + m] = f2tf32(S[m*68 + off+2]);
            As[(q*4+3)*72 + m] = f2tf32(S[m*68 + off+3]);
        }
        {   // stage B: g_bc [16 k][64 t]
            int krow = tid >> 4, tb = tid & 15;
            size_t bb = ((size_t)lh * 128 + c * 16 + krow) * 64;
            #pragma unroll
            for (int j = 0; j < 4; ++j) {
                int tt = tb + 16 * j;
                Bs[krow * 72 + tt] = g_bc[bb + tt];
            }
        }
        __syncthreads();
        #pragma unroll
        for (int ks = 0; ks < 2; ++ks) {
            int kb = ks * 8;
            #pragma unroll
            for (int mi = 0; mi < 2; ++mi) {
                int mr = wm2 * 32 + mi * 16 + g;
                uint32_t a0 = As[(kb + t4)     * 72 + mr];
                uint32_t a1 = As[(kb + t4)     * 72 + mr + 8];
                uint32_t a2 = As[(kb + t4 + 4) * 72 + mr];
                uint32_t a3 = As[(kb + t4 + 4) * 72 + mr + 8];
                #pragma unroll
                for (int nj = 0; nj < 2; ++nj) {
                    int nc = wn2 * 16 + nj * 8 + g;
                    uint32_t b0 = Bs[(kb + t4)     * 72 + nc];
                    uint32_t b1 = Bs[(kb + t4 + 4) * 72 + nc];
                    mma_tf32(acc2[mi][nj], a0, a1, a2, a3, b0, b1);
                }
            }
        }
    }
    __syncthreads();
    #pragma unroll
    for (int mi = 0; mi < 2; ++mi) {
        #pragma unroll
        for (int nj = 0; nj < 2; ++nj) {
            int colp = wn2 * 16 + nj * 8 + t4 * 2;
            #pragma unroll
            for (int rr = 0; rr < 2; ++rr) {
                int r = wm2 * 32 + mi * 16 + g + rr * 8;
                float y0 = Ys[r * 68 + colp]     + acc2[mi][nj][rr*2+0];
                float y1 = Ys[r * 68 + colp + 1] + acc2[mi][nj][rr*2+1];
                y0 = gelu1(y0); y1 = gelu1(y1);
                int b  = b0 + (r >> 5);
                int blk = r & 31;
                float* dst = &g_yt[((size_t)(b * HH + h)) * LL + blk * TB + colp];
                *reinterpret_cast<float2*>(dst) = make_float2(y0, y1);
            }
        }
    }
}

#define ASTR 136
#define BSTR 72
__global__ void __launch_bounds__(256) glu_gemm_mma(
        const float* __restrict__ W1, const float* __restrict__ W2,
        const float* __restrict__ b1, const float* __restrict__ b2) {
    __shared__ uint32_t As [32 * ASTR];
    __shared__ uint32_t Bs1[32 * BSTR];
    __shared__ uint32_t Bs2[32 * BSTR];
    int tid  = threadIdx.x;
    int wid  = tid >> 5;
    int lane = tid & 31;
    int g    = lane >> 2;
    int t    = lane & 3;
    int wm   = wid & 3;
    int wn   = wid >> 2;
    int m0  = blockIdx.x * 128;
    int n0  = blockIdx.y * 64;
    int bch = m0 >> 11;
    int ml0 = m0 & 2047;

    float acc1[2][4][4];
    float acc2[2][4][4];
    #pragma unroll
    for (int mi = 0; mi < 2; ++mi)
        #pragma unroll
        for (int nj = 0; nj < 4; ++nj)
            #pragma unroll
            for (int r = 0; r < 4; ++r) { acc1[mi][nj][r] = 0.f; acc2[mi][nj][r] = 0.f; }

    for (int kc = 0; kc < HH; kc += 32) {
        __syncthreads();
        #pragma unroll
        for (int it = 0; it < 4; ++it) {
            int item = it * 256 + tid;
            int krow = item >> 5;
            int c4   = (item & 31) * 4;
            const float* src = &g_yt[(size_t)(bch * HH + kc + krow) * LL + ml0 + c4];
            float4 v = *reinterpret_cast<const float4*>(src);
            uint32_t* dst = &As[krow * ASTR + c4];
            asm volatile("st.shared.v4.b32 [%0], {%1,%2,%3,%4};"
                :: "l"(dst), "r"(f2tf32(v.x)), "r"(f2tf32(v.y)),
                   "r"(f2tf32(v.z)), "r"(f2tf32(v.w)) : "memory");
        }
        #pragma unroll
        for (int it = 0; it < 2; ++it) {
            int item = it * 256 + tid;
            int gg = item & 63;
            int kq = item >> 6;
            size_t off = (size_t)(n0 + gg) * HH + kc + kq * 4;
            float4 w1 = *reinterpret_cast<const float4*>(&W1[off]);
            float4 w2 = *reinterpret_cast<const float4*>(&W2[off]);
            int kb = kq * 4;
            Bs1[(kb+0) * BSTR + gg] = f2tf32(w1.x);
            Bs1[(kb+1) * BSTR + gg] = f2tf32(w1.y);
            Bs1[(kb+2) * BSTR + gg] = f2tf32(w1.z);
            Bs1[(kb+3) * BSTR + gg] = f2tf32(w1.w);
            Bs2[(kb+0) * BSTR + gg] = f2tf32(w2.x);
            Bs2[(kb+1) * BSTR + gg] = f2tf32(w2.y);
            Bs2[(kb+2) * BSTR + gg] = f2tf32(w2.z);
            Bs2[(kb+3) * BSTR + gg] = f2tf32(w2.w);
        }
        __syncthreads();
        #pragma unroll
        for (int ks = 0; ks < 4; ++ks) {
            int kb = ks * 8;
            uint32_t af[2][4];
            #pragma unroll
            for (int mi = 0; mi < 2; ++mi) {
                int mrow = wm * 32 + mi * 16;
                af[mi][0] = As[(kb + t)     * ASTR + mrow + g];
                af[mi][1] = As[(kb + t)     * ASTR + mrow + g + 8];
                af[mi][2] = As[(kb + t + 4) * ASTR + mrow + g];
                af[mi][3] = As[(kb + t + 4) * ASTR + mrow + g + 8];
            }
            #pragma unroll
            for (int nj = 0; nj < 4; ++nj) {
                int ncol = wn * 32 + nj * 8 + g;
                uint32_t bA0 = Bs1[(kb + t)     * BSTR + ncol];
                uint32_t bA1 = Bs1[(kb + t + 4) * BSTR + ncol];
                uint32_t bB0 = Bs2[(kb + t)     * BSTR + ncol];
                uint32_t bB1 = Bs2[(kb + t + 4) * BSTR + ncol];
                #pragma unroll
                for (int mi = 0; mi < 2; ++mi) {
                    mma_tf32(acc1[mi][nj], af[mi][0], af[mi][1], af[mi][2], af[mi][3], bA0, bA1);
                    mma_tf32(acc2[mi][nj], af[mi][0], af[mi][1], af[mi][2], af[mi][3], bB0, bB1);
                }
            }
        }
    }
    #pragma unroll
    for (int nj = 0; nj < 4; ++nj) {
        int ncol = n0 + wn * 32 + nj * 8 + t * 2;
        float bb1a = b1[ncol], bb1b = b1[ncol + 1];
        float bb2a = b2[ncol], bb2b = b2[ncol + 1];
        #pragma unroll
        for (int mi = 0; mi < 2; ++mi) {
            #pragma unroll
            for (int rr = 0; rr < 2; ++rr) {
                int mrow = m0 + wm * 32 + mi * 16 + g + rr * 8;
                float* hp = &g_h[(size_t)mrow * HH + ncol];
                float2 hv = *reinterpret_cast<float2*>(hp);
                float d1a = acc1[mi][nj][rr * 2 + 0] + bb1a;
                float d1b = acc1[mi][nj][rr * 2 + 1] + bb1b;
                float d2a = acc2[mi][nj][rr * 2 + 0] + bb2a;
                float d2b = acc2[mi][nj][rr * 2 + 1] + bb2b;
                hv.x += d1a * (1.0f / (1.0f + expf(-d2a)));
                hv.y += d1b * (1.0f / (1.0f + expf(-d2b)));
                *reinterpret_cast<float2*>(hp) = hv;
            }
        }
    }
}

__global__ void dec_kernel(const float* __restrict__ dw,
                           const float* __restrict__ db,
                           float* __restrict__ out) {
    int warp = (blockIdx.x * blockDim.x + threadIdx.x) >> 5;
    int lane = threadIdx.x & 31;
    const float* row = g_h + (size_t)warp * HH;
    float hr[8];
    #pragma unroll
    for (int k = 0; k < 8; ++k) hr[k] = row[lane + 32 * k];
    for (int o = 0; o < OUTD; ++o) {
        const float* wrow = dw + o * HH + lane;
        float acc = 0.0f;
        #pragma unroll
        for (int k = 0; k < 8; ++k) acc = fmaf(hr[k], wrow[32 * k], acc);
        #pragma unroll
        for (int m = 16; m; m >>= 1) acc += __shfl_xor_sync(0xffffffffu, acc, m);
        if (lane == 0) out[(size_t)warp * OUTD + o] = acc + db[o];
    }
}

extern "C" void kernel_launch(void* const* d_in, const int* in_sizes, int n_in,
                              void* d_out, int out_size) {
    const float* x     = (const float*)d_in[0];
    const float* enc_w = (const float*)d_in[1];
    const float* enc_b = (const float*)d_in[2];
    const float* lre   = (const float*)d_in[3];
    const float* lim   = (const float*)d_in[4];
    const float* cre   = (const float*)d_in[5];
    const float* cim   = (const float*)d_in[6];
    const float* dd    = (const float*)d_in[7];
    const float* lstep = (const float*)d_in[8];
    const float* lns   = (const float*)d_in[9];
    const float* lnb   = (const float*)d_in[10];
    const float* ow    = (const float*)d_in[11];
    const float* ob    = (const float*)d_in[12];
    const float* o2w   = (const float*)d_in[13];
    const float* o2b   = (const float*)d_in[14];
    const float* dw    = (const float*)d_in[15];
    const float* db    = (const float*)d_in[16];
    float* out = (float*)d_out;

    cudaFuncSetAttribute(ssm_conv,
                         cudaFuncAttributeMaxDynamicSharedMemorySize, SSM_SMEM);

    ssm_prep<<<(LH * NN) / 256, 256>>>(lre, lim, cre, cim, lstep);
    kv_build<<<(LH * TB * 32) / 256, 256>>>(dd);
    pack_bl<<<(LH * 64 * 192) / 256, 256>>>();
    pack_bc<<<(LH * 128 * 64) / 256, 256>>>();

    enc_kernel<<<(BB * LL) / 16, 256>>>(x, enc_w, enc_b);

    for (int li = 0; li < NLAY; ++li) {
        ln_kernel<<<(BB * LL) / 32, 256>>>(lns + li * HH, lnb + li * HH);
        ssm_conv<<<dim3(8, HH), 256, SSM_SMEM>>>(li);
        glu_gemm_mma<<<dim3((BB * LL) / 128, HH / 64), 256>>>(
            ow + li * HH * HH, o2w + li * HH * HH,
            ob + li * HH, o2b + li * HH);
    }

    dec_kernel<<<(BB * LL) / 8, 256>>>(dw, db, out);
}